// round 2
// baseline (speedup 1.0000x reference)
#include <cuda_runtime.h>

#define NN 100000
#define EE 1600000
#define DD 64

// ---- scratch (static device globals; no allocation anywhere) ----
__device__ float g_deg_row[NN];
__device__ float g_deg[NN];
__device__ float g_dinv[NN];
__device__ float g_norm[EE];
__device__ __align__(16) float g_x[NN * DD];
__device__ __align__(16) float g_h[NN * DD];
__device__ __align__(16) float g_y[NN * DD];
__device__ float g_h3[NN];

// ---------------- precompute kernels ----------------

__global__ void k_init(float* __restrict__ dr, float* __restrict__ dg, int N) {
    int i = blockIdx.x * blockDim.x + threadIdx.x;
    if (i < N) { dr[i] = 0.f; dg[i] = 1.f; }  // dg starts at 1.0: self-loop weight
}

__global__ void k_degrow(const int* __restrict__ src,
                         const float* __restrict__ ev,
                         float* __restrict__ dr, int E) {
    int e = blockIdx.x * blockDim.x + threadIdx.x;
    if (e < E) atomicAdd(&dr[src[e]], ev[e]);
}

__global__ void k_guard(float* __restrict__ dr, int N) {
    int i = blockIdx.x * blockDim.x + threadIdx.x;
    if (i < N && dr[i] <= 0.f) dr[i] = 1.f;
}

__global__ void k_what(const int* __restrict__ src,
                       const int* __restrict__ dst,
                       const float* __restrict__ ev,
                       const float* __restrict__ dr,
                       float* __restrict__ nm,
                       float* __restrict__ dg, int E) {
    int e = blockIdx.x * blockDim.x + threadIdx.x;
    if (e >= E) return;
    int s = src[e], d = dst[e];
    float w = ev[e] / (dr[s] * dr[d]);
    nm[e] = w;                  // temporarily store w_hat
    atomicAdd(&dg[d], w);
}

__global__ void k_dinv(const float* __restrict__ dg, float* __restrict__ dv, int N) {
    int i = blockIdx.x * blockDim.x + threadIdx.x;
    if (i < N) {
        float g = dg[i];
        dv[i] = (g > 0.f) ? rsqrtf(g) : 0.f;
    }
}

__global__ void k_normfin(const int* __restrict__ src,
                          const int* __restrict__ dst,
                          const float* __restrict__ dv,
                          float* __restrict__ nm, int E) {
    int e = blockIdx.x * blockDim.x + threadIdx.x;
    if (e >= E) return;
    nm[e] = nm[e] * dv[src[e]] * dv[dst[e]];
}

// x = feat / rowsum(feat); one warp per row (64 cols -> 2 per lane)
__global__ void k_xnorm(const float* __restrict__ feat, float* __restrict__ x, int N) {
    int warp = (blockIdx.x * blockDim.x + threadIdx.x) >> 5;
    int lane = threadIdx.x & 31;
    if (warp >= N) return;
    const float* fr = feat + (size_t)warp * DD;
    float a = fr[lane], b = fr[lane + 32];
    float s = a + b;
#pragma unroll
    for (int o = 16; o > 0; o >>= 1) s += __shfl_xor_sync(0xffffffffu, s, o);
    float inv = 1.f / s;
    float* xr = x + (size_t)warp * DD;
    xr[lane] = a * inv;
    xr[lane + 32] = b * inv;
}

// ---------------- layer kernels ----------------

// h = (relu?)x @ W ;  y = b + dinv^2 * h  (self-loop contribution pre-added)
// block = 256 threads, 16 rows/block, W staged in smem.
template <bool RELU>
__global__ void k_gemm(const float* __restrict__ x, const float* __restrict__ W,
                       const float* __restrict__ b, const float* __restrict__ dv,
                       float* __restrict__ h, float* __restrict__ y, int N) {
    __shared__ __align__(16) float Ws[DD * DD];
    __shared__ float xs[16 * (DD + 1)];
    int tid = threadIdx.x;
    for (int i = tid; i < DD * DD; i += 256) Ws[i] = W[i];
    int row0 = blockIdx.x * 16;
    for (int i = tid; i < 16 * DD; i += 256) {
        int r = i >> 6, c = i & 63;
        int row = row0 + r;
        float v = (row < N) ? x[(size_t)row * DD + c] : 0.f;
        if (RELU) v = fmaxf(v, 0.f);
        xs[r * (DD + 1) + c] = v;
    }
    __syncthreads();
    int r = tid >> 4;
    int cg = (tid & 15) << 2;
    int row = row0 + r;
    if (row >= N) return;
    const float* xr = &xs[r * (DD + 1)];
    float4 acc = make_float4(0.f, 0.f, 0.f, 0.f);
#pragma unroll
    for (int k = 0; k < DD; k++) {
        float xv = xr[k];
        float4 wv = *(const float4*)&Ws[k * DD + cg];
        acc.x += xv * wv.x; acc.y += xv * wv.y;
        acc.z += xv * wv.z; acc.w += xv * wv.w;
    }
    float d = dv[row];
    float d2 = d * d;
    float4 bb = *(const float4*)&b[cg];
    *(float4*)&h[(size_t)row * DD + cg] = acc;
    float4 yy = make_float4(bb.x + d2 * acc.x, bb.y + d2 * acc.y,
                            bb.z + d2 * acc.z, bb.w + d2 * acc.w);
    *(float4*)&y[(size_t)row * DD + cg] = yy;
}

// y[dst] += norm[e] * h[src] ; 16 threads per edge, float4 RED.128 atomics
__global__ void k_agg(const float* __restrict__ h, float* __restrict__ y,
                      const int* __restrict__ src,
                      const int* __restrict__ dst,
                      const float* __restrict__ nm, int E) {
    long long gid = (long long)blockIdx.x * blockDim.x + threadIdx.x;
    int e = (int)(gid >> 4);
    if (e >= E) return;
    int c = ((int)gid & 15) << 2;
    int s = src[e], d = dst[e];
    float nv = nm[e];
    float4 hv = *(const float4*)&h[(size_t)s * DD + c];
    float4 m = make_float4(nv * hv.x, nv * hv.y, nv * hv.z, nv * hv.w);
    atomicAdd((float4*)&y[(size_t)d * DD + c], m);
}

// layer 3: h3[n] = relu(x[n]) . W3 ; out[n] = b3 + dinv^2*h3[n]
__global__ void k_gemm3(const float* __restrict__ x, const float* __restrict__ W3,
                        const float* __restrict__ b3, const float* __restrict__ dv,
                        float* __restrict__ h3, float* __restrict__ out, int N) {
    int warp = (blockIdx.x * blockDim.x + threadIdx.x) >> 5;
    int lane = threadIdx.x & 31;
    if (warp >= N) return;
    const float* xr = x + (size_t)warp * DD;
    float v0 = fmaxf(xr[lane], 0.f);
    float v1 = fmaxf(xr[lane + 32], 0.f);
    float s = v0 * W3[lane] + v1 * W3[lane + 32];
#pragma unroll
    for (int o = 16; o > 0; o >>= 1) s += __shfl_xor_sync(0xffffffffu, s, o);
    if (lane == 0) {
        h3[warp] = s;
        float d = dv[warp];
        out[warp] = b3[0] + d * d * s;
    }
}

__global__ void k_agg3(const float* __restrict__ h3, float* __restrict__ out,
                       const int* __restrict__ src,
                       const int* __restrict__ dst,
                       const float* __restrict__ nm, int E) {
    int e = blockIdx.x * blockDim.x + threadIdx.x;
    if (e >= E) return;
    atomicAdd(&out[dst[e]], nm[e] * h3[src[e]]);
}

// ---------------- launch ----------------

extern "C" void kernel_launch(void* const* d_in, const int* in_sizes, int n_in,
                              void* d_out, int out_size) {
    const float* feat = (const float*)d_in[0];
    const int*   ei   = (const int*)d_in[1];   // int32! (JAX x64 disabled downcasts int64)
    const float* ev   = (const float*)d_in[2];
    const float* W1   = (const float*)d_in[3];
    const float* b1   = (const float*)d_in[4];
    const float* W2   = (const float*)d_in[5];
    const float* b2   = (const float*)d_in[6];
    const float* W3   = (const float*)d_in[7];
    const float* b3   = (const float*)d_in[8];
    float* out = (float*)d_out;

    int N = in_sizes[0] / DD;
    int E = in_sizes[2];
    const int* src = ei;
    const int* dst = ei + E;

    float *dr, *dg, *dv, *nm, *px, *ph, *py, *ph3;
    cudaGetSymbolAddress((void**)&dr,  g_deg_row);
    cudaGetSymbolAddress((void**)&dg,  g_deg);
    cudaGetSymbolAddress((void**)&dv,  g_dinv);
    cudaGetSymbolAddress((void**)&nm,  g_norm);
    cudaGetSymbolAddress((void**)&px,  g_x);
    cudaGetSymbolAddress((void**)&ph,  g_h);
    cudaGetSymbolAddress((void**)&py,  g_y);
    cudaGetSymbolAddress((void**)&ph3, g_h3);

    int nb  = (N + 255) / 256;
    int ebl = (E + 255) / 256;

    // precompute normalization
    k_init   <<<nb, 256>>>(dr, dg, N);
    k_degrow <<<ebl, 256>>>(src, ev, dr, E);
    k_guard  <<<nb, 256>>>(dr, N);
    k_what   <<<ebl, 256>>>(src, dst, ev, dr, nm, dg, E);
    k_dinv   <<<nb, 256>>>(dg, dv, N);
    k_normfin<<<ebl, 256>>>(src, dst, dv, nm, E);

    // x = feat / rowsum
    k_xnorm<<<(N * 32 + 255) / 256, 256>>>(feat, px, N);

    int gemm_blocks = (N + 15) / 16;
    long long agg_threads = (long long)E * 16;
    int agg_blocks = (int)((agg_threads + 255) / 256);

    // layer 1: x -> h, y ; aggregate ; (relu folded into next gemm's read)
    k_gemm<false><<<gemm_blocks, 256>>>(px, W1, b1, dv, ph, py, N);
    k_agg        <<<agg_blocks, 256>>>(ph, py, src, dst, nm, E);

    // layer 2: relu(y) -> h, x(reused as y2) ; aggregate
    k_gemm<true> <<<gemm_blocks, 256>>>(py, W2, b2, dv, ph, px, N);
    k_agg        <<<agg_blocks, 256>>>(ph, px, src, dst, nm, E);

    // layer 3: relu(x) -> scalar per node ; aggregate into d_out
    k_gemm3<<<(N * 32 + 255) / 256, 256>>>(px, W3, b3, dv, ph3, out, N);
    k_agg3 <<<ebl, 256>>>(ph3, out, src, dst, nm, E);
}

// round 3
// speedup vs baseline: 1.1285x; 1.1285x over previous
#include <cuda_runtime.h>

#define NN 100000
#define EE 1600000
#define DD 64
#define SCAN_BS 1024
#define SCAN_NB ((NN + SCAN_BS - 1) / SCAN_BS)   // 98

// ---- scratch (static device globals; no allocation anywhere) ----
__device__ float g_dr[NN];                    // deg_row
__device__ int   g_cnt[NN];                   // dst histogram
__device__ int   g_rp[NN + 1];                // CSR row_ptr (by dst)
__device__ int   g_cur[NN];                   // scatter cursors
__device__ int   g_bsum[SCAN_NB];             // scan block sums
__device__ float g_dv[NN];                    // dinv
__device__ int   g_es[EE];                    // CSR: src per sorted edge
__device__ float g_ew[EE];                    // CSR: w_hat per sorted edge
__device__ __align__(16) float g_x[NN * DD];  // normalized features
__device__ __align__(16) float g_hs[NN * DD]; // dinv * (x@W)
__device__ __align__(16) float g_acc[NN * DD];// aggregated
__device__ float g_h3s[NN];

__device__ __forceinline__ float guard1(float v) { return v > 0.f ? v : 1.f; }

// ---------------- precompute ----------------

__global__ void k_zero(float* __restrict__ dr, int* __restrict__ cnt, int N) {
    int i = blockIdx.x * blockDim.x + threadIdx.x;
    if (i < N) { dr[i] = 0.f; cnt[i] = 0; }
}

// deg_row[src] += ev ; cnt[dst] += 1
__global__ void k_pre1(const int* __restrict__ src, const int* __restrict__ dst,
                       const float* __restrict__ ev,
                       float* __restrict__ dr, int* __restrict__ cnt, int E) {
    int e = blockIdx.x * blockDim.x + threadIdx.x;
    if (e >= E) return;
    atomicAdd(&dr[src[e]], ev[e]);
    atomicAdd(&cnt[dst[e]], 1);
}

// block-level exclusive scan of cnt -> rp ; block totals -> bsum
__global__ void k_scan1(const int* __restrict__ cnt, int* __restrict__ rp,
                        int* __restrict__ bsum, int N) {
    __shared__ int sh[SCAN_BS];
    int t = threadIdx.x;
    int i = blockIdx.x * SCAN_BS + t;
    int v = (i < N) ? cnt[i] : 0;
    sh[t] = v;
    __syncthreads();
#pragma unroll
    for (int o = 1; o < SCAN_BS; o <<= 1) {
        int add = (t >= o) ? sh[t - o] : 0;
        __syncthreads();
        sh[t] += add;
        __syncthreads();
    }
    if (i < N) rp[i] = sh[t] - v;               // exclusive within block
    if (t == SCAN_BS - 1) bsum[blockIdx.x] = sh[t];
}

// exclusive scan of bsum (nb <= 128), single block
__global__ void k_scan2(int* __restrict__ bsum, int nb) {
    __shared__ int sh[128];
    int t = threadIdx.x;
    int v = (t < nb) ? bsum[t] : 0;
    sh[t] = v;
    __syncthreads();
#pragma unroll
    for (int o = 1; o < 128; o <<= 1) {
        int add = (t >= o) ? sh[t - o] : 0;
        __syncthreads();
        sh[t] += add;
        __syncthreads();
    }
    if (t < nb) bsum[t] = sh[t] - v;
}

// rp[i] += block offset ; cursor = rp ; rp[N] = E
__global__ void k_scan3(int* __restrict__ rp, int* __restrict__ cur,
                        const int* __restrict__ bsum, int N, int E) {
    int i = blockIdx.x * blockDim.x + threadIdx.x;
    if (i >= N) return;
    int r = rp[i] + bsum[i >> 10];
    rp[i] = r;
    cur[i] = r;
    if (i == 0) rp[N] = E;
}

// fused w_hat compute + CSR scatter (sorted by dst)
__global__ void k_scatter(const int* __restrict__ src, const int* __restrict__ dst,
                          const float* __restrict__ ev, const float* __restrict__ dr,
                          int* __restrict__ cur,
                          int* __restrict__ es, float* __restrict__ ew, int E) {
    int e = blockIdx.x * blockDim.x + threadIdx.x;
    if (e >= E) return;
    int s = src[e], d = dst[e];
    float w = ev[e] / (guard1(__ldg(&dr[s])) * guard1(__ldg(&dr[d])));
    int p = atomicAdd(&cur[d], 1);
    es[p] = s;
    ew[p] = w;
}

// dinv[n] = rsqrt(1 + sum of ew over row n)  (warp per node, coalesced)
__global__ void k_dinv(const int* __restrict__ rp, const float* __restrict__ ew,
                       float* __restrict__ dv, int N) {
    int n = (blockIdx.x * blockDim.x + threadIdx.x) >> 5;
    int lane = threadIdx.x & 31;
    if (n >= N) return;
    int beg = rp[n], end = rp[n + 1];
    float s = 0.f;
    for (int j = beg + lane; j < end; j += 32) s += ew[j];
#pragma unroll
    for (int o = 16; o > 0; o >>= 1) s += __shfl_xor_sync(0xffffffffu, s, o);
    if (lane == 0) dv[n] = rsqrtf(1.f + s);
}

// x = feat / rowsum(feat); one warp per row
__global__ void k_xnorm(const float* __restrict__ feat, float* __restrict__ x, int N) {
    int n = (blockIdx.x * blockDim.x + threadIdx.x) >> 5;
    int lane = threadIdx.x & 31;
    if (n >= N) return;
    const float* fr = feat + (size_t)n * DD;
    float a = fr[lane], b = fr[lane + 32];
    float s = a + b;
#pragma unroll
    for (int o = 16; o > 0; o >>= 1) s += __shfl_xor_sync(0xffffffffu, s, o);
    float inv = 1.f / s;
    float* xr = x + (size_t)n * DD;
    xr[lane] = a * inv;
    xr[lane + 32] = b * inv;
}

// ---------------- layers ----------------

// MODE 0: v = in[row,c]                   (layer 1 input, already normalized)
// MODE 1: v = relu(bp[c] + dv[row]*in[row,c])   (finalize prev layer + relu)
// Output: hs[row,c] = dv[row] * (v @ W)[c]
template <int MODE>
__global__ void k_gemm(const float* __restrict__ in, const float* __restrict__ W,
                       const float* __restrict__ bp, const float* __restrict__ dv,
                       float* __restrict__ hs, int N) {
    __shared__ __align__(16) float Ws[DD * DD];
    __shared__ float xs[16 * (DD + 1)];
    __shared__ float bs[DD];
    int tid = threadIdx.x;
    for (int i = tid; i < DD * DD; i += 256) Ws[i] = W[i];
    if (MODE == 1 && tid < DD) bs[tid] = bp[tid];
    int row0 = blockIdx.x * 16;
    __syncthreads();
    for (int i = tid; i < 16 * DD; i += 256) {
        int r = i >> 6, c = i & 63;
        int row = row0 + r;
        float v = 0.f;
        if (row < N) {
            v = in[(size_t)row * DD + c];
            if (MODE == 1) v = fmaxf(bs[c] + dv[row] * v, 0.f);
        }
        xs[r * (DD + 1) + c] = v;
    }
    __syncthreads();
    int r = tid >> 4;
    int cg = (tid & 15) << 2;
    int row = row0 + r;
    if (row >= N) return;
    const float* xr = &xs[r * (DD + 1)];
    float4 acc = make_float4(0.f, 0.f, 0.f, 0.f);
#pragma unroll
    for (int k = 0; k < DD; k++) {
        float xv = xr[k];
        float4 wv = *(const float4*)&Ws[k * DD + cg];
        acc.x += xv * wv.x; acc.y += xv * wv.y;
        acc.z += xv * wv.z; acc.w += xv * wv.w;
    }
    float d = dv[row];
    acc.x *= d; acc.y *= d; acc.z *= d; acc.w *= d;
    *(float4*)&hs[(size_t)row * DD + cg] = acc;
}

// acc[n] = hs[n] + sum_{edges into n} ew * hs[src]  (warp per node, no atomics)
__global__ void k_aggcsr(const float* __restrict__ hs, float* __restrict__ acc,
                         const int* __restrict__ rp, const int* __restrict__ es,
                         const float* __restrict__ ew, int N) {
    int n = (blockIdx.x * blockDim.x + threadIdx.x) >> 5;
    int lane = threadIdx.x & 31;
    if (n >= N) return;
    int c2 = lane << 1;
    float2 a = *(const float2*)&hs[(size_t)n * DD + c2];   // self loop (dinv folded)
    int beg = rp[n], end = rp[n + 1];
    for (int j0 = beg; j0 < end; j0 += 32) {
        int jl = j0 + lane;
        int sv = 0; float wv = 0.f;
        if (jl < end) { sv = es[jl]; wv = ew[jl]; }
        int m = min(32, end - j0);
        for (int k = 0; k < m; k++) {
            int s = __shfl_sync(0xffffffffu, sv, k);
            float w = __shfl_sync(0xffffffffu, wv, k);
            float2 hv = *(const float2*)&hs[(size_t)s * DD + c2];
            a.x += w * hv.x;
            a.y += w * hv.y;
        }
    }
    *(float2*)&acc[(size_t)n * DD + c2] = a;
}

// layer 3 matvec: h3s[n] = dv[n] * ( relu(b2 + dv[n]*acc2[n,:]) . W3 )
__global__ void k_gemm3(const float* __restrict__ acc2, const float* __restrict__ W3,
                        const float* __restrict__ b2, const float* __restrict__ dv,
                        float* __restrict__ h3s, int N) {
    int n = (blockIdx.x * blockDim.x + threadIdx.x) >> 5;
    int lane = threadIdx.x & 31;
    if (n >= N) return;
    float d = dv[n];
    const float* xr = acc2 + (size_t)n * DD;
    float v0 = fmaxf(__ldg(&b2[lane])      + d * xr[lane],      0.f);
    float v1 = fmaxf(__ldg(&b2[lane + 32]) + d * xr[lane + 32], 0.f);
    float s = v0 * __ldg(&W3[lane]) + v1 * __ldg(&W3[lane + 32]);
#pragma unroll
    for (int o = 16; o > 0; o >>= 1) s += __shfl_xor_sync(0xffffffffu, s, o);
    if (lane == 0) h3s[n] = d * s;
}

// out[n] = b3 + dv[n] * ( h3s[n] + sum ew*h3s[src] )   (warp per node)
__global__ void k_agg3(const float* __restrict__ h3s, float* __restrict__ out,
                       const int* __restrict__ rp, const int* __restrict__ es,
                       const float* __restrict__ ew, const float* __restrict__ b3,
                       const float* __restrict__ dv, int N) {
    int n = (blockIdx.x * blockDim.x + threadIdx.x) >> 5;
    int lane = threadIdx.x & 31;
    if (n >= N) return;
    int beg = rp[n], end = rp[n + 1];
    float t = 0.f;
    for (int j = beg + lane; j < end; j += 32)
        t += ew[j] * __ldg(&h3s[es[j]]);
#pragma unroll
    for (int o = 16; o > 0; o >>= 1) t += __shfl_xor_sync(0xffffffffu, t, o);
    if (lane == 0) out[n] = __ldg(&b3[0]) + dv[n] * (h3s[n] + t);
}

// ---------------- launch ----------------

extern "C" void kernel_launch(void* const* d_in, const int* in_sizes, int n_in,
                              void* d_out, int out_size) {
    const float* feat = (const float*)d_in[0];
    const int*   ei   = (const int*)d_in[1];   // int32 (JAX x64 disabled)
    const float* ev   = (const float*)d_in[2];
    const float* W1   = (const float*)d_in[3];
    const float* b1   = (const float*)d_in[4];
    const float* W2   = (const float*)d_in[5];
    const float* b2   = (const float*)d_in[6];
    const float* W3   = (const float*)d_in[7];
    const float* b3   = (const float*)d_in[8];
    float* out = (float*)d_out;

    int N = in_sizes[0] / DD;
    int E = in_sizes[2];
    const int* src = ei;
    const int* dst = ei + E;

    float *dr, *dv, *ew, *px, *phs, *pacc, *ph3s;
    int *cnt, *rp, *cur, *bsum, *es;
    cudaGetSymbolAddress((void**)&dr,   g_dr);
    cudaGetSymbolAddress((void**)&cnt,  g_cnt);
    cudaGetSymbolAddress((void**)&rp,   g_rp);
    cudaGetSymbolAddress((void**)&cur,  g_cur);
    cudaGetSymbolAddress((void**)&bsum, g_bsum);
    cudaGetSymbolAddress((void**)&dv,   g_dv);
    cudaGetSymbolAddress((void**)&es,   g_es);
    cudaGetSymbolAddress((void**)&ew,   g_ew);
    cudaGetSymbolAddress((void**)&px,   g_x);
    cudaGetSymbolAddress((void**)&phs,  g_hs);
    cudaGetSymbolAddress((void**)&pacc, g_acc);
    cudaGetSymbolAddress((void**)&ph3s, g_h3s);

    int nb   = (N + 255) / 256;
    int ebl  = (E + 255) / 256;
    int wnb  = (N * 32 + 255) / 256;          // warp-per-node grids
    int gemm_blocks = (N + 15) / 16;

    // CSR build + normalization precompute
    k_zero   <<<nb, 256>>>(dr, cnt, N);
    k_pre1   <<<ebl, 256>>>(src, dst, ev, dr, cnt, E);
    k_scan1  <<<SCAN_NB, SCAN_BS>>>(cnt, rp, bsum, N);
    k_scan2  <<<1, 128>>>(bsum, SCAN_NB);
    k_scan3  <<<nb, 256>>>(rp, cur, bsum, N, E);
    k_scatter<<<ebl, 256>>>(src, dst, ev, dr, cur, es, ew, E);
    k_dinv   <<<wnb, 256>>>(rp, ew, dv, N);

    // features
    k_xnorm<<<wnb, 256>>>(feat, px, N);

    // layer 1
    k_gemm<0><<<gemm_blocks, 256>>>(px, W1, nullptr, dv, phs, N);
    k_aggcsr <<<wnb, 256>>>(phs, pacc, rp, es, ew, N);
    // layer 2 (b1 + dinv scaling + relu folded into staging)
    k_gemm<1><<<gemm_blocks, 256>>>(pacc, W2, b1, dv, phs, N);
    k_aggcsr <<<wnb, 256>>>(phs, pacc, rp, es, ew, N);
    // layer 3
    k_gemm3<<<wnb, 256>>>(pacc, W3, b2, dv, ph3s, N);
    k_agg3 <<<wnb, 256>>>(ph3s, out, rp, es, ew, b3, dv, N);
}

// round 4
// speedup vs baseline: 1.5791x; 1.3993x over previous
#include <cuda_runtime.h>

#define NN 100000
#define EE 1600000
#define DD 64
#define SCAN_BS 1024
#define SCAN_NB ((NN + SCAN_BS - 1) / SCAN_BS)   // 98

// ---- scratch (static device globals; no allocation anywhere) ----
__device__ float  g_dr[NN];                    // deg_row
__device__ int    g_cnt[NN];                   // dst histogram
__device__ int    g_rp[NN + 1];                // CSR row_ptr (by dst)
__device__ int    g_cur[NN];                   // scatter cursors
__device__ int    g_bsum[SCAN_NB];             // scan block sums
__device__ float  g_dv[NN];                    // dinv
__device__ float2 g_epk[EE];                   // CSR: packed (src bits, w_hat)
__device__ __align__(16) float g_x[NN * DD];   // normalized features
__device__ __align__(16) float g_hs[NN * DD];  // dinv * (x@W)
__device__ __align__(16) float g_acc[NN * DD]; // aggregated
__device__ float g_h3s[NN];

__device__ __forceinline__ float guard1(float v) { return v > 0.f ? v : 1.f; }

// ---------------- precompute ----------------

__global__ void k_zero(float* __restrict__ dr, int* __restrict__ cnt, int N) {
    int i = blockIdx.x * blockDim.x + threadIdx.x;
    if (i < N) { dr[i] = 0.f; cnt[i] = 0; }
}

// deg_row[src] += ev ; cnt[dst] += 1
__global__ void k_pre1(const int* __restrict__ src, const int* __restrict__ dst,
                       const float* __restrict__ ev,
                       float* __restrict__ dr, int* __restrict__ cnt, int E) {
    int e = blockIdx.x * blockDim.x + threadIdx.x;
    if (e >= E) return;
    atomicAdd(&dr[src[e]], ev[e]);
    atomicAdd(&cnt[dst[e]], 1);
}

// block-level exclusive scan of cnt -> rp ; block totals -> bsum
__global__ void k_scan1(const int* __restrict__ cnt, int* __restrict__ rp,
                        int* __restrict__ bsum, int N) {
    __shared__ int sh[SCAN_BS];
    int t = threadIdx.x;
    int i = blockIdx.x * SCAN_BS + t;
    int v = (i < N) ? cnt[i] : 0;
    sh[t] = v;
    __syncthreads();
#pragma unroll
    for (int o = 1; o < SCAN_BS; o <<= 1) {
        int add = (t >= o) ? sh[t - o] : 0;
        __syncthreads();
        sh[t] += add;
        __syncthreads();
    }
    if (i < N) rp[i] = sh[t] - v;               // exclusive within block
    if (t == SCAN_BS - 1) bsum[blockIdx.x] = sh[t];
}

// rp[i] += prefix(bsum) ; cursor = rp ; rp[N] = E.
// Each block redundantly scans the 98 block sums in smem (no separate kernel).
__global__ void k_scan3(int* __restrict__ rp, int* __restrict__ cur,
                        const int* __restrict__ bsum, int N, int E) {
    __shared__ int sh[128];
    int t = threadIdx.x;
    if (t < 128) sh[t] = (t < SCAN_NB) ? bsum[t] : 0;
    __syncthreads();
#pragma unroll
    for (int o = 1; o < 128; o <<= 1) {
        int add = (t >= o && t < 128) ? sh[t - o] : 0;
        __syncthreads();
        if (t < 128) sh[t] += add;               // inclusive scan
        __syncthreads();
    }
    int i = blockIdx.x * blockDim.x + t;
    if (i >= N) return;
    int blk = i >> 10;
    int off = blk ? sh[blk - 1] : 0;
    int r = rp[i] + off;
    rp[i] = r;
    cur[i] = r;
    if (i == 0) rp[N] = E;
}

// fused w_hat compute + CSR scatter (sorted by dst), packed (src, w)
__global__ void k_scatter(const int* __restrict__ src, const int* __restrict__ dst,
                          const float* __restrict__ ev, const float* __restrict__ dr,
                          int* __restrict__ cur, float2* __restrict__ epk, int E) {
    int e = blockIdx.x * blockDim.x + threadIdx.x;
    if (e >= E) return;
    int s = src[e], d = dst[e];
    float w = ev[e] / (guard1(__ldg(&dr[s])) * guard1(__ldg(&dr[d])));
    int p = atomicAdd(&cur[d], 1);
    epk[p] = make_float2(__int_as_float(s), w);
}

// warp per node: dinv[n] = rsqrt(1 + sum ew) AND x = feat / rowsum(feat)
__global__ void k_prep(const int* __restrict__ rp, const float2* __restrict__ epk,
                       const float* __restrict__ feat,
                       float* __restrict__ dv, float* __restrict__ x, int N) {
    int n = (blockIdx.x * blockDim.x + threadIdx.x) >> 5;
    int lane = threadIdx.x & 31;
    if (n >= N) return;
    int beg = rp[n], end = rp[n + 1];
    float s = 0.f;
    for (int j = beg + lane; j < end; j += 32) s += __ldg(&epk[j]).y;
    const float* fr = feat + (size_t)n * DD;
    float a = fr[lane], b = fr[lane + 32];
    float fs = a + b;
#pragma unroll
    for (int o = 16; o > 0; o >>= 1) {
        s  += __shfl_xor_sync(0xffffffffu, s, o);
        fs += __shfl_xor_sync(0xffffffffu, fs, o);
    }
    if (lane == 0) dv[n] = rsqrtf(1.f + s);
    float inv = 1.f / fs;
    float* xr = x + (size_t)n * DD;
    xr[lane] = a * inv;
    xr[lane + 32] = b * inv;
}

// ---------------- layers ----------------

// MODE 0: v = in[row,c]
// MODE 1: v = relu(bp[c] + dv[row]*in[row,c])
// Output: hs[row,c] = dv[row] * (v @ W)[c]
// 64x64 tile per block (256 thr), 4 rows x 4 cols per thread.
#define XS 68
template <int MODE>
__global__ void k_gemm(const float* __restrict__ in, const float* __restrict__ W,
                       const float* __restrict__ bp, const float* __restrict__ dv,
                       float* __restrict__ hs, int N) {
    __shared__ __align__(16) float Ws[DD * DD];
    __shared__ __align__(16) float xsT[DD * XS];   // [k][row]
    __shared__ float bs[DD];
    __shared__ float dvs[64];
    int tid = threadIdx.x;
    int row0 = blockIdx.x * 64;
    for (int i = tid; i < DD * DD; i += 256) Ws[i] = W[i];
    if (tid < DD) bs[tid] = (MODE == 1) ? bp[tid] : 0.f;
    if (tid < 64) {
        int row = row0 + tid;
        dvs[tid] = (row < N) ? dv[row] : 0.f;
    }
    __syncthreads();
#pragma unroll
    for (int it = 0; it < 16; it++) {
        int i = it * 256 + tid;
        int r = i >> 6, c = i & 63;
        int row = row0 + r;
        float v = 0.f;
        if (row < N) {
            v = in[(size_t)row * DD + c];
            if (MODE == 1) v = fmaxf(bs[c] + dvs[r] * v, 0.f);
        }
        xsT[c * XS + r] = v;
    }
    __syncthreads();
    int tx = (tid & 15) << 2;   // col base
    int ty = (tid >> 4) << 2;   // row base
    float4 a0 = make_float4(0.f,0.f,0.f,0.f), a1 = a0, a2 = a0, a3 = a0;
#pragma unroll
    for (int k = 0; k < DD; k++) {
        float4 xv = *(const float4*)&xsT[k * XS + ty];
        float4 wv = *(const float4*)&Ws[k * DD + tx];
        a0.x += xv.x*wv.x; a0.y += xv.x*wv.y; a0.z += xv.x*wv.z; a0.w += xv.x*wv.w;
        a1.x += xv.y*wv.x; a1.y += xv.y*wv.y; a1.z += xv.y*wv.z; a1.w += xv.y*wv.w;
        a2.x += xv.z*wv.x; a2.y += xv.z*wv.y; a2.z += xv.z*wv.z; a2.w += xv.z*wv.w;
        a3.x += xv.w*wv.x; a3.y += xv.w*wv.y; a3.z += xv.w*wv.z; a3.w += xv.w*wv.w;
    }
#pragma unroll
    for (int rr = 0; rr < 4; rr++) {
        int row = row0 + ty + rr;
        if (row >= N) break;
        float d = dvs[ty + rr];
        float4 a = (rr == 0) ? a0 : (rr == 1) ? a1 : (rr == 2) ? a2 : a3;
        a.x *= d; a.y *= d; a.z *= d; a.w *= d;
        *(float4*)&hs[(size_t)row * DD + tx] = a;
    }
}

// acc[n] = hs[n] + sum_{edges into n} w * hs[src]  (warp per node, smem-staged)
__global__ void k_aggcsr(const float* __restrict__ hs, float* __restrict__ acc,
                         const int* __restrict__ rp, const float2* __restrict__ epk,
                         int N) {
    __shared__ float2 st[8][32];
    int wid  = threadIdx.x >> 5;
    int lane = threadIdx.x & 31;
    int n = (blockIdx.x * blockDim.x + threadIdx.x) >> 5;
    if (n >= N) return;
    int c2 = lane << 1;
    float2 a = *(const float2*)&hs[(size_t)n * DD + c2];   // self loop
    int beg = rp[n], end = rp[n + 1];
    for (int j0 = beg; j0 < end; j0 += 32) {
        int m = end - j0;
        int jl = j0 + ((lane < m) ? lane : (m - 1));
        st[wid][lane] = __ldg(&epk[jl]);
        __syncwarp();
        if (m >= 32) {
#pragma unroll 8
            for (int k = 0; k < 32; k++) {
                float2 p = st[wid][k];
                int s = __float_as_int(p.x);
                float2 hv = *(const float2*)&hs[(size_t)s * DD + c2];
                a.x += p.y * hv.x;
                a.y += p.y * hv.y;
            }
        } else {
            for (int k = 0; k < m; k++) {
                float2 p = st[wid][k];
                int s = __float_as_int(p.x);
                float2 hv = *(const float2*)&hs[(size_t)s * DD + c2];
                a.x += p.y * hv.x;
                a.y += p.y * hv.y;
            }
        }
        __syncwarp();
    }
    *(float2*)&acc[(size_t)n * DD + c2] = a;
}

// layer 3 matvec: h3s[n] = dv[n] * ( relu(b2 + dv[n]*acc2[n,:]) . W3 )
__global__ void k_gemm3(const float* __restrict__ acc2, const float* __restrict__ W3,
                        const float* __restrict__ b2, const float* __restrict__ dv,
                        float* __restrict__ h3s, int N) {
    int n = (blockIdx.x * blockDim.x + threadIdx.x) >> 5;
    int lane = threadIdx.x & 31;
    if (n >= N) return;
    float d = dv[n];
    const float* xr = acc2 + (size_t)n * DD;
    float v0 = fmaxf(__ldg(&b2[lane])      + d * xr[lane],      0.f);
    float v1 = fmaxf(__ldg(&b2[lane + 32]) + d * xr[lane + 32], 0.f);
    float s = v0 * __ldg(&W3[lane]) + v1 * __ldg(&W3[lane + 32]);
#pragma unroll
    for (int o = 16; o > 0; o >>= 1) s += __shfl_xor_sync(0xffffffffu, s, o);
    if (lane == 0) h3s[n] = d * s;
}

// out[n] = b3 + dv[n] * ( h3s[n] + sum w*h3s[src] )   (warp per node)
__global__ void k_agg3(const float* __restrict__ h3s, float* __restrict__ out,
                       const int* __restrict__ rp, const float2* __restrict__ epk,
                       const float* __restrict__ b3, const float* __restrict__ dv,
                       int N) {
    int n = (blockIdx.x * blockDim.x + threadIdx.x) >> 5;
    int lane = threadIdx.x & 31;
    if (n >= N) return;
    int beg = rp[n], end = rp[n + 1];
    float t = 0.f;
    for (int j = beg + lane; j < end; j += 32) {
        float2 p = __ldg(&epk[j]);
        t += p.y * __ldg(&h3s[__float_as_int(p.x)]);
    }
#pragma unroll
    for (int o = 16; o > 0; o >>= 1) t += __shfl_xor_sync(0xffffffffu, t, o);
    if (lane == 0) out[n] = __ldg(&b3[0]) + dv[n] * (h3s[n] + t);
}

// ---------------- launch ----------------

extern "C" void kernel_launch(void* const* d_in, const int* in_sizes, int n_in,
                              void* d_out, int out_size) {
    const float* feat = (const float*)d_in[0];
    const int*   ei   = (const int*)d_in[1];   // int32 (JAX x64 disabled)
    const float* ev   = (const float*)d_in[2];
    const float* W1   = (const float*)d_in[3];
    const float* b1   = (const float*)d_in[4];
    const float* W2   = (const float*)d_in[5];
    const float* b2   = (const float*)d_in[6];
    const float* W3   = (const float*)d_in[7];
    const float* b3   = (const float*)d_in[8];
    float* out = (float*)d_out;

    int N = in_sizes[0] / DD;
    int E = in_sizes[2];
    const int* src = ei;
    const int* dst = ei + E;

    float *dr, *dv, *px, *phs, *pacc, *ph3s;
    float2* epk;
    int *cnt, *rp, *cur, *bsum;
    cudaGetSymbolAddress((void**)&dr,   g_dr);
    cudaGetSymbolAddress((void**)&cnt,  g_cnt);
    cudaGetSymbolAddress((void**)&rp,   g_rp);
    cudaGetSymbolAddress((void**)&cur,  g_cur);
    cudaGetSymbolAddress((void**)&bsum, g_bsum);
    cudaGetSymbolAddress((void**)&dv,   g_dv);
    cudaGetSymbolAddress((void**)&epk,  g_epk);
    cudaGetSymbolAddress((void**)&px,   g_x);
    cudaGetSymbolAddress((void**)&phs,  g_hs);
    cudaGetSymbolAddress((void**)&pacc, g_acc);
    cudaGetSymbolAddress((void**)&ph3s, g_h3s);

    int nb  = (N + 255) / 256;
    int ebl = (E + 255) / 256;
    int wnb = (N * 32 + 255) / 256;            // warp-per-node grids
    int gemm_blocks = (N + 63) / 64;

    // CSR build + normalization precompute
    k_zero   <<<nb, 256>>>(dr, cnt, N);
    k_pre1   <<<ebl, 256>>>(src, dst, ev, dr, cnt, E);
    k_scan1  <<<SCAN_NB, SCAN_BS>>>(cnt, rp, bsum, N);
    k_scan3  <<<nb, 256>>>(rp, cur, bsum, N, E);
    k_scatter<<<ebl, 256>>>(src, dst, ev, dr, cur, epk, E);
    k_prep   <<<wnb, 256>>>(rp, epk, feat, dv, px, N);

    // layer 1
    k_gemm<0><<<gemm_blocks, 256>>>(px, W1, nullptr, dv, phs, N);
    k_aggcsr <<<wnb, 256>>>(phs, pacc, rp, epk, N);
    // layer 2 (b1 + dinv scaling + relu folded into staging)
    k_gemm<1><<<gemm_blocks, 256>>>(pacc, W2, b1, dv, phs, N);
    k_aggcsr <<<wnb, 256>>>(phs, pacc, rp, epk, N);
    // layer 3
    k_gemm3<<<wnb, 256>>>(pacc, W3, b2, dv, ph3s, N);
    k_agg3 <<<wnb, 256>>>(ph3s, out, rp, epk, b3, dv, N);
}

// round 5
// speedup vs baseline: 1.7629x; 1.1164x over previous
#include <cuda_runtime.h>
#include <cuda_fp16.h>

#define NN 100000
#define EE 1600000
#define DD 64
#define SCAN_BS 1024
#define SCAN_NB ((NN + SCAN_BS - 1) / SCAN_BS)   // 98

// ---- scratch (static device globals; no allocation anywhere) ----
__device__ float  g_dr[NN];                    // deg_row
__device__ int    g_cnt[NN];                   // dst histogram
__device__ int    g_rp[NN + 1];                // CSR row_ptr (by dst)
__device__ int    g_cur[NN];                   // scatter cursors
__device__ int    g_bsum[SCAN_NB];             // scan block sums
__device__ float  g_dv[NN];                    // dinv
__device__ float  g_ri[NN];                    // 1 / rowsum(feat)
__device__ float2 g_epk[EE];                   // CSR: packed (src bits, w_hat)
__device__ __align__(16) __half g_hsh[NN * DD];   // fp16: dinv * (x@W)
__device__ __align__(16) float  g_acc[NN * DD];   // aggregated (fp32)
__device__ float g_h3s[NN];

__device__ __forceinline__ float guard1(float v) { return v > 0.f ? v : 1.f; }

// ---------------- precompute ----------------

__global__ void k_zero(float* __restrict__ dr, int* __restrict__ cnt, int N) {
    int i = blockIdx.x * blockDim.x + threadIdx.x;
    if (i < N) { dr[i] = 0.f; cnt[i] = 0; }
}

// deg_row[src] += ev ; cnt[dst] += 1
__global__ void k_pre1(const int* __restrict__ src, const int* __restrict__ dst,
                       const float* __restrict__ ev,
                       float* __restrict__ dr, int* __restrict__ cnt, int E) {
    int e = blockIdx.x * blockDim.x + threadIdx.x;
    if (e >= E) return;
    atomicAdd(&dr[src[e]], ev[e]);
    atomicAdd(&cnt[dst[e]], 1);
}

// block-level exclusive scan of cnt -> rp ; block totals -> bsum (shfl-based)
__global__ void k_scan1(const int* __restrict__ cnt, int* __restrict__ rp,
                        int* __restrict__ bsum, int N) {
    __shared__ int ws[32];
    int t = threadIdx.x;
    int lane = t & 31, wid = t >> 5;
    int i = blockIdx.x * SCAN_BS + t;
    int v = (i < N) ? cnt[i] : 0;
    int x = v;
#pragma unroll
    for (int o = 1; o < 32; o <<= 1) {
        int y = __shfl_up_sync(0xffffffffu, x, o);
        if (lane >= o) x += y;
    }
    if (lane == 31) ws[wid] = x;
    __syncthreads();
    if (wid == 0) {
        int s = ws[lane];
#pragma unroll
        for (int o = 1; o < 32; o <<= 1) {
            int y = __shfl_up_sync(0xffffffffu, s, o);
            if (lane >= o) s += y;
        }
        ws[lane] = s;
    }
    __syncthreads();
    int incl = x + (wid ? ws[wid - 1] : 0);
    if (i < N) rp[i] = incl - v;                // exclusive within block
    if (t == SCAN_BS - 1) bsum[blockIdx.x] = incl;
}

// rp[i] += prefix(bsum) ; cursor = rp ; rp[N] = E (redundant per-block scan)
__global__ void k_scan3(int* __restrict__ rp, int* __restrict__ cur,
                        const int* __restrict__ bsum, int N, int E) {
    __shared__ int sh[128];
    int t = threadIdx.x;
    if (t < 128) sh[t] = (t < SCAN_NB) ? bsum[t] : 0;
    __syncthreads();
#pragma unroll
    for (int o = 1; o < 128; o <<= 1) {
        int add = (t >= o && t < 128) ? sh[t - o] : 0;
        __syncthreads();
        if (t < 128) sh[t] += add;               // inclusive scan
        __syncthreads();
    }
    int i = blockIdx.x * blockDim.x + t;
    if (i >= N) return;
    int blk = i >> 10;
    int off = blk ? sh[blk - 1] : 0;
    int r = rp[i] + off;
    rp[i] = r;
    cur[i] = r;
    if (i == 0) rp[N] = E;
}

// fused w_hat compute + CSR scatter (sorted by dst), packed (src, w)
__global__ void k_scatter(const int* __restrict__ src, const int* __restrict__ dst,
                          const float* __restrict__ ev, const float* __restrict__ dr,
                          int* __restrict__ cur, float2* __restrict__ epk, int E) {
    int e = blockIdx.x * blockDim.x + threadIdx.x;
    if (e >= E) return;
    int s = src[e], d = dst[e];
    float w = ev[e] / (guard1(__ldg(&dr[s])) * guard1(__ldg(&dr[d])));
    int p = atomicAdd(&cur[d], 1);
    epk[p] = make_float2(__int_as_float(s), w);
}

// warp per node: dinv[n] = rsqrt(1 + sum ew) AND rowinv[n] = 1/rowsum(feat)
__global__ void k_prep(const int* __restrict__ rp, const float2* __restrict__ epk,
                       const float* __restrict__ feat,
                       float* __restrict__ dv, float* __restrict__ ri, int N) {
    int n = (blockIdx.x * blockDim.x + threadIdx.x) >> 5;
    int lane = threadIdx.x & 31;
    if (n >= N) return;
    int beg = rp[n], end = rp[n + 1];
    float s = 0.f;
    for (int j = beg + lane; j < end; j += 32) s += __ldg(&epk[j]).y;
    const float* fr = feat + (size_t)n * DD;
    float fs = fr[lane] + fr[lane + 32];
#pragma unroll
    for (int o = 16; o > 0; o >>= 1) {
        s  += __shfl_xor_sync(0xffffffffu, s, o);
        fs += __shfl_xor_sync(0xffffffffu, fs, o);
    }
    if (lane == 0) {
        dv[n] = rsqrtf(1.f + s);
        ri[n] = 1.f / fs;
    }
}

// ---------------- layers ----------------

// MODE 0: v = in[row,c] * rowinv[row]          (aux = rowinv, per-row)
// MODE 1: v = relu(aux[c] + dv[row]*in[row,c]) (aux = bias, per-col)
// Output: hsh[row,c] = half( dv[row] * (v @ W)[c] )
#define XS 68
template <int MODE>
__global__ void k_gemm(const float* __restrict__ in, const float* __restrict__ W,
                       const float* __restrict__ aux, const float* __restrict__ dv,
                       __half* __restrict__ hsh, int N) {
    __shared__ __align__(16) float Ws[DD * DD];
    __shared__ __align__(16) float xsT[DD * XS];   // [k][row]
    __shared__ float auxs[DD];
    __shared__ float dvs[64];
    int tid = threadIdx.x;
    int row0 = blockIdx.x * 64;
    for (int i = tid; i < DD * DD; i += 256) Ws[i] = W[i];
    if (MODE == 1 && tid < DD) auxs[tid] = aux[tid];
    if (tid < 64) {
        int row = row0 + tid;
        dvs[tid] = (row < N) ? dv[row] : 0.f;
        if (MODE == 0) auxs[tid] = (row < N) ? aux[row] : 0.f;  // rowinv
    }
    __syncthreads();
#pragma unroll
    for (int it = 0; it < 16; it++) {
        int i = it * 256 + tid;
        int r = i >> 6, c = i & 63;
        int row = row0 + r;
        float v = 0.f;
        if (row < N) {
            v = in[(size_t)row * DD + c];
            if (MODE == 0) v *= auxs[r];
            else           v = fmaxf(auxs[c] + dvs[r] * v, 0.f);
        }
        xsT[c * XS + r] = v;
    }
    __syncthreads();
    int tx = (tid & 15) << 2;   // col base
    int ty = (tid >> 4) << 2;   // row base
    float4 a0 = make_float4(0.f,0.f,0.f,0.f), a1 = a0, a2 = a0, a3 = a0;
#pragma unroll
    for (int k = 0; k < DD; k++) {
        float4 xv = *(const float4*)&xsT[k * XS + ty];
        float4 wv = *(const float4*)&Ws[k * DD + tx];
        a0.x += xv.x*wv.x; a0.y += xv.x*wv.y; a0.z += xv.x*wv.z; a0.w += xv.x*wv.w;
        a1.x += xv.y*wv.x; a1.y += xv.y*wv.y; a1.z += xv.y*wv.z; a1.w += xv.y*wv.w;
        a2.x += xv.z*wv.x; a2.y += xv.z*wv.y; a2.z += xv.z*wv.z; a2.w += xv.z*wv.w;
        a3.x += xv.w*wv.x; a3.y += xv.w*wv.y; a3.z += xv.w*wv.z; a3.w += xv.w*wv.w;
    }
#pragma unroll
    for (int rr = 0; rr < 4; rr++) {
        int row = row0 + ty + rr;
        if (row >= N) break;
        float d = dvs[ty + rr];
        float4 a = (rr == 0) ? a0 : (rr == 1) ? a1 : (rr == 2) ? a2 : a3;
        __half2 p0 = __floats2half2_rn(d * a.x, d * a.y);
        __half2 p1 = __floats2half2_rn(d * a.z, d * a.w);
        uint2 o;
        o.x = *(unsigned int*)&p0;
        o.y = *(unsigned int*)&p1;
        *(uint2*)&hsh[(size_t)row * DD + tx] = o;
    }
}

// acc[n] = hs[n] + sum_{edges into n} w * hs[src]  (warp per node; fp16 gather,
// 128B = one line per edge per warp)
__global__ void k_aggcsr(const __half* __restrict__ hsh, float* __restrict__ acc,
                         const int* __restrict__ rp, const float2* __restrict__ epk,
                         int N) {
    __shared__ float2 st[8][32];
    int wid  = threadIdx.x >> 5;
    int lane = threadIdx.x & 31;
    int n = (blockIdx.x * blockDim.x + threadIdx.x) >> 5;
    if (n >= N) return;
    int c2 = lane << 1;
    float2 a = __half22float2(*(const __half2*)&hsh[(size_t)n * DD + c2]);  // self
    int beg = rp[n], end = rp[n + 1];
    for (int j0 = beg; j0 < end; j0 += 32) {
        int m = end - j0;
        int jl = j0 + ((lane < m) ? lane : (m - 1));
        st[wid][lane] = __ldg(&epk[jl]);
        __syncwarp();
        if (m >= 32) {
#pragma unroll 8
            for (int k = 0; k < 32; k++) {
                float2 p = st[wid][k];
                int s = __float_as_int(p.x);
                float2 hv = __half22float2(*(const __half2*)&hsh[(size_t)s * DD + c2]);
                a.x += p.y * hv.x;
                a.y += p.y * hv.y;
            }
        } else {
            for (int k = 0; k < m; k++) {
                float2 p = st[wid][k];
                int s = __float_as_int(p.x);
                float2 hv = __half22float2(*(const __half2*)&hsh[(size_t)s * DD + c2]);
                a.x += p.y * hv.x;
                a.y += p.y * hv.y;
            }
        }
        __syncwarp();
    }
    *(float2*)&acc[(size_t)n * DD + c2] = a;
}

// layer 3 matvec: h3s[n] = dv[n] * ( relu(b2 + dv[n]*acc2[n,:]) . W3 )
__global__ void k_gemm3(const float* __restrict__ acc2, const float* __restrict__ W3,
                        const float* __restrict__ b2, const float* __restrict__ dv,
                        float* __restrict__ h3s, int N) {
    int n = (blockIdx.x * blockDim.x + threadIdx.x) >> 5;
    int lane = threadIdx.x & 31;
    if (n >= N) return;
    float d = dv[n];
    const float* xr = acc2 + (size_t)n * DD;
    float v0 = fmaxf(__ldg(&b2[lane])      + d * xr[lane],      0.f);
    float v1 = fmaxf(__ldg(&b2[lane + 32]) + d * xr[lane + 32], 0.f);
    float s = v0 * __ldg(&W3[lane]) + v1 * __ldg(&W3[lane + 32]);
#pragma unroll
    for (int o = 16; o > 0; o >>= 1) s += __shfl_xor_sync(0xffffffffu, s, o);
    if (lane == 0) h3s[n] = d * s;
}

// out[n] = b3 + dv[n] * ( h3s[n] + sum w*h3s[src] )   (warp per node)
__global__ void k_agg3(const float* __restrict__ h3s, float* __restrict__ out,
                       const int* __restrict__ rp, const float2* __restrict__ epk,
                       const float* __restrict__ b3, const float* __restrict__ dv,
                       int N) {
    int n = (blockIdx.x * blockDim.x + threadIdx.x) >> 5;
    int lane = threadIdx.x & 31;
    if (n >= N) return;
    int beg = rp[n], end = rp[n + 1];
    float t = 0.f;
    for (int j = beg + lane; j < end; j += 32) {
        float2 p = __ldg(&epk[j]);
        t += p.y * __ldg(&h3s[__float_as_int(p.x)]);
    }
#pragma unroll
    for (int o = 16; o > 0; o >>= 1) t += __shfl_xor_sync(0xffffffffu, t, o);
    if (lane == 0) out[n] = __ldg(&b3[0]) + dv[n] * (h3s[n] + t);
}

// ---------------- launch ----------------

extern "C" void kernel_launch(void* const* d_in, const int* in_sizes, int n_in,
                              void* d_out, int out_size) {
    const float* feat = (const float*)d_in[0];
    const int*   ei   = (const int*)d_in[1];   // int32 (JAX x64 disabled)
    const float* ev   = (const float*)d_in[2];
    const float* W1   = (const float*)d_in[3];
    const float* b1   = (const float*)d_in[4];
    const float* W2   = (const float*)d_in[5];
    const float* b2   = (const float*)d_in[6];
    const float* W3   = (const float*)d_in[7];
    const float* b3   = (const float*)d_in[8];
    float* out = (float*)d_out;

    int N = in_sizes[0] / DD;
    int E = in_sizes[2];
    const int* src = ei;
    const int* dst = ei + E;

    float *dr, *dv, *ri, *pacc, *ph3s;
    __half* phsh;
    float2* epk;
    int *cnt, *rp, *cur, *bsum;
    cudaGetSymbolAddress((void**)&dr,   g_dr);
    cudaGetSymbolAddress((void**)&cnt,  g_cnt);
    cudaGetSymbolAddress((void**)&rp,   g_rp);
    cudaGetSymbolAddress((void**)&cur,  g_cur);
    cudaGetSymbolAddress((void**)&bsum, g_bsum);
    cudaGetSymbolAddress((void**)&dv,   g_dv);
    cudaGetSymbolAddress((void**)&ri,   g_ri);
    cudaGetSymbolAddress((void**)&epk,  g_epk);
    cudaGetSymbolAddress((void**)&phsh, g_hsh);
    cudaGetSymbolAddress((void**)&pacc, g_acc);
    cudaGetSymbolAddress((void**)&ph3s, g_h3s);

    int nb  = (N + 255) / 256;
    int ebl = (E + 255) / 256;
    int wnb = (N * 32 + 255) / 256;            // warp-per-node grids
    int gemm_blocks = (N + 63) / 64;

    // CSR build + normalization precompute
    k_zero   <<<nb, 256>>>(dr, cnt, N);
    k_pre1   <<<ebl, 256>>>(src, dst, ev, dr, cnt, E);
    k_scan1  <<<SCAN_NB, SCAN_BS>>>(cnt, rp, bsum, N);
    k_scan3  <<<nb, 256>>>(rp, cur, bsum, N, E);
    k_scatter<<<ebl, 256>>>(src, dst, ev, dr, cur, epk, E);
    k_prep   <<<wnb, 256>>>(rp, epk, feat, dv, ri, N);

    // layer 1 (feat normalization folded into staging via rowinv)
    k_gemm<0><<<gemm_blocks, 256>>>(feat, W1, ri, dv, phsh, N);
    k_aggcsr <<<wnb, 256>>>(phsh, pacc, rp, epk, N);
    // layer 2 (b1 + dinv scaling + relu folded into staging)
    k_gemm<1><<<gemm_blocks, 256>>>(pacc, W2, b1, dv, phsh, N);
    k_aggcsr <<<wnb, 256>>>(phsh, pacc, rp, epk, N);
    // layer 3
    k_gemm3<<<wnb, 256>>>(pacc, W3, b2, dv, ph3s, N);
    k_agg3 <<<wnb, 256>>>(ph3s, out, rp, epk, b3, dv, N);
}

// round 6
// speedup vs baseline: 2.0304x; 1.1518x over previous
#include <cuda_runtime.h>
#include <cuda_fp16.h>

#define NN 100000
#define EE 1600000
#define DD 64
#define SCAN_BS 1024
#define SCAN_NB ((NN + SCAN_BS - 1) / SCAN_BS)   // 98

// ---- scratch (static device globals; no allocation anywhere) ----
__device__ float  g_dr[NN];                    // deg_row
__device__ int    g_cnt[NN];                   // dst histogram
__device__ int    g_rp[NN + 1];                // CSR row_ptr (by dst)
__device__ int    g_cur[NN];                   // scatter cursors
__device__ int    g_bsum[SCAN_NB];             // scan block sums
__device__ float  g_dv[NN];                    // dinv
__device__ float  g_ri[NN];                    // 1 / rowsum(feat)
__device__ float2 g_epk[EE];                   // CSR: packed (src bits, w_hat)
__device__ __align__(16) __half g_hsh[NN * DD];   // fp16: dinv * (x@W)
__device__ __align__(16) float  g_acc[NN * DD];   // aggregated (fp32)
__device__ float g_h3s[NN];

__device__ __forceinline__ float guard1(float v) { return v > 0.f ? v : 1.f; }

__device__ __forceinline__ unsigned f2tf32(float v) {
    unsigned t;
    asm("cvt.rna.tf32.f32 %0, %1;" : "=r"(t) : "f"(v));
    return t;
}

__device__ __forceinline__ void mma_tf32(float* d,
                                         unsigned a0, unsigned a1, unsigned a2, unsigned a3,
                                         unsigned b0, unsigned b1) {
    asm volatile(
        "mma.sync.aligned.m16n8k8.row.col.f32.tf32.tf32.f32 "
        "{%0,%1,%2,%3}, {%4,%5,%6,%7}, {%8,%9}, {%0,%1,%2,%3};"
        : "+f"(d[0]), "+f"(d[1]), "+f"(d[2]), "+f"(d[3])
        : "r"(a0), "r"(a1), "r"(a2), "r"(a3), "r"(b0), "r"(b1));
}

// ---------------- precompute ----------------

__global__ void k_zero(float* __restrict__ dr, int* __restrict__ cnt, int N) {
    int i = blockIdx.x * blockDim.x + threadIdx.x;
    if (i < N) { dr[i] = 0.f; cnt[i] = 0; }
}

// deg_row[src] += ev ; cnt[dst] += 1
__global__ void k_pre1(const int* __restrict__ src, const int* __restrict__ dst,
                       const float* __restrict__ ev,
                       float* __restrict__ dr, int* __restrict__ cnt, int E) {
    int e = blockIdx.x * blockDim.x + threadIdx.x;
    if (e >= E) return;
    atomicAdd(&dr[src[e]], ev[e]);
    atomicAdd(&cnt[dst[e]], 1);
}

// block-level exclusive scan of cnt -> rp ; block totals -> bsum (shfl-based)
__global__ void k_scan1(const int* __restrict__ cnt, int* __restrict__ rp,
                        int* __restrict__ bsum, int N) {
    __shared__ int ws[32];
    int t = threadIdx.x;
    int lane = t & 31, wid = t >> 5;
    int i = blockIdx.x * SCAN_BS + t;
    int v = (i < N) ? cnt[i] : 0;
    int x = v;
#pragma unroll
    for (int o = 1; o < 32; o <<= 1) {
        int y = __shfl_up_sync(0xffffffffu, x, o);
        if (lane >= o) x += y;
    }
    if (lane == 31) ws[wid] = x;
    __syncthreads();
    if (wid == 0) {
        int s = ws[lane];
#pragma unroll
        for (int o = 1; o < 32; o <<= 1) {
            int y = __shfl_up_sync(0xffffffffu, s, o);
            if (lane >= o) s += y;
        }
        ws[lane] = s;
    }
    __syncthreads();
    int incl = x + (wid ? ws[wid - 1] : 0);
    if (i < N) rp[i] = incl - v;                // exclusive within block
    if (t == SCAN_BS - 1) bsum[blockIdx.x] = incl;
}

// rp[i] += prefix(bsum) ; cursor = rp ; rp[N] = E (redundant per-block scan)
__global__ void k_scan3(int* __restrict__ rp, int* __restrict__ cur,
                        const int* __restrict__ bsum, int N, int E) {
    __shared__ int sh[128];
    int t = threadIdx.x;
    if (t < 128) sh[t] = (t < SCAN_NB) ? bsum[t] : 0;
    __syncthreads();
#pragma unroll
    for (int o = 1; o < 128; o <<= 1) {
        int add = (t >= o && t < 128) ? sh[t - o] : 0;
        __syncthreads();
        if (t < 128) sh[t] += add;               // inclusive scan
        __syncthreads();
    }
    int i = blockIdx.x * blockDim.x + t;
    if (i >= N) return;
    int blk = i >> 10;
    int off = blk ? sh[blk - 1] : 0;
    int r = rp[i] + off;
    rp[i] = r;
    cur[i] = r;
    if (i == 0) rp[N] = E;
}

// fused w_hat compute + CSR scatter (sorted by dst), packed (src, w)
__global__ void k_scatter(const int* __restrict__ src, const int* __restrict__ dst,
                          const float* __restrict__ ev, const float* __restrict__ dr,
                          int* __restrict__ cur, float2* __restrict__ epk, int E) {
    int e = blockIdx.x * blockDim.x + threadIdx.x;
    if (e >= E) return;
    int s = src[e], d = dst[e];
    float w = ev[e] / (guard1(__ldg(&dr[s])) * guard1(__ldg(&dr[d])));
    int p = atomicAdd(&cur[d], 1);
    epk[p] = make_float2(__int_as_float(s), w);
}

// warp per node: dinv[n] = rsqrt(1 + sum ew) AND rowinv[n] = 1/rowsum(feat)
__global__ void k_prep(const int* __restrict__ rp, const float2* __restrict__ epk,
                       const float* __restrict__ feat,
                       float* __restrict__ dv, float* __restrict__ ri, int N) {
    int n = (blockIdx.x * blockDim.x + threadIdx.x) >> 5;
    int lane = threadIdx.x & 31;
    if (n >= N) return;
    int beg = rp[n], end = rp[n + 1];
    float s = 0.f;
    for (int j = beg + lane; j < end; j += 32) s += __ldg(&epk[j]).y;
    const float* fr = feat + (size_t)n * DD;
    float fs = fr[lane] + fr[lane + 32];
#pragma unroll
    for (int o = 16; o > 0; o >>= 1) {
        s  += __shfl_xor_sync(0xffffffffu, s, o);
        fs += __shfl_xor_sync(0xffffffffu, fs, o);
    }
    if (lane == 0) {
        dv[n] = rsqrtf(1.f + s);
        ri[n] = 1.f / fs;
    }
}

// ---------------- layers ----------------

// Tensor-core GEMM: 64x64 tile per block (256 thr = 8 warps), tf32 mma.sync,
// fp32 accumulate, fp16 output.
// MODE 0: v = in[row,c]; output scale = dv[row]*rowinv[row]   (aux = rowinv)
// MODE 1: v = relu(aux[c] + dv[row]*in[row,c]); scale = dv[row] (aux = bias)
#define XA 68   // xs stride: bank = 4*g + tig -> conflict-free A-frag loads
#define WB 72   // Ws stride: bank = 8*tig + g -> conflict-free B-frag loads
template <int MODE>
__global__ void k_gemm(const float* __restrict__ in, const float* __restrict__ W,
                       const float* __restrict__ aux, const float* __restrict__ dv,
                       __half* __restrict__ hsh, int N) {
    __shared__ float Ws[DD * WB];
    __shared__ float xs[DD * XA];
    __shared__ float bs[DD];
    __shared__ float dvs[DD];
    __shared__ float scal[DD];
    int tid = threadIdx.x;
    int row0 = blockIdx.x * 64;

    // stage W (cvt to tf32 once)
#pragma unroll
    for (int it = 0; it < 16; it++) {
        int i = it * 256 + tid;
        Ws[(i >> 6) * WB + (i & 63)] = __uint_as_float(f2tf32(W[i]));
    }
    if (MODE == 1 && tid < DD) bs[tid] = aux[tid];
    if (tid < 64) {
        int row = row0 + tid;
        float d = (row < N) ? dv[row] : 0.f;
        dvs[tid] = d;
        scal[tid] = (MODE == 0) ? d * ((row < N) ? aux[row] : 0.f) : d;
    }
    __syncthreads();

    // stage x rows (transform + cvt to tf32)
#pragma unroll
    for (int it = 0; it < 16; it++) {
        int i = it * 256 + tid;
        int r = i >> 6, c = i & 63;
        int row = row0 + r;
        float v = 0.f;
        if (row < N) {
            v = in[(size_t)row * DD + c];
            if (MODE == 1) v = fmaxf(bs[c] + dvs[r] * v, 0.f);
        }
        xs[r * XA + c] = __uint_as_float(f2tf32(v));
    }
    __syncthreads();

    int warp = tid >> 5, lane = tid & 31;
    int m0 = (warp & 3) << 4;    // 4 m-tiles of 16 rows
    int n0 = (warp >> 2) << 5;   // 2 n-tiles of 32 cols
    int g = lane >> 2, tig = lane & 3;

    float acc[4][4];
#pragma unroll
    for (int s = 0; s < 4; s++) { acc[s][0] = acc[s][1] = acc[s][2] = acc[s][3] = 0.f; }

#pragma unroll
    for (int ks = 0; ks < 8; ks++) {
        int k0 = ks << 3;
        unsigned a0 = __float_as_uint(xs[(m0 + g)     * XA + k0 + tig]);
        unsigned a1 = __float_as_uint(xs[(m0 + g + 8) * XA + k0 + tig]);
        unsigned a2 = __float_as_uint(xs[(m0 + g)     * XA + k0 + tig + 4]);
        unsigned a3 = __float_as_uint(xs[(m0 + g + 8) * XA + k0 + tig + 4]);
#pragma unroll
        for (int sub = 0; sub < 4; sub++) {
            int n = n0 + (sub << 3) + g;
            unsigned b0 = __float_as_uint(Ws[(k0 + tig)     * WB + n]);
            unsigned b1 = __float_as_uint(Ws[(k0 + tig + 4) * WB + n]);
            mma_tf32(acc[sub], a0, a1, a2, a3, b0, b1);
        }
    }

    // epilogue: D(row, col) per mma layout; scale and emit fp16
    int rlo = m0 + g, rhi = m0 + g + 8;
    int row_lo = row0 + rlo, row_hi = row0 + rhi;
    float s0 = scal[rlo], s1 = scal[rhi];
#pragma unroll
    for (int sub = 0; sub < 4; sub++) {
        int col = n0 + (sub << 3) + (tig << 1);
        if (row_lo < N) {
            __half2 h = __floats2half2_rn(s0 * acc[sub][0], s0 * acc[sub][1]);
            *(__half2*)&hsh[(size_t)row_lo * DD + col] = h;
        }
        if (row_hi < N) {
            __half2 h = __floats2half2_rn(s1 * acc[sub][2], s1 * acc[sub][3]);
            *(__half2*)&hsh[(size_t)row_hi * DD + col] = h;
        }
    }
}

// acc[n] = hs[n] + sum_{edges into n} w * hs[src]  (warp per node; fp16 gather,
// 128B = one line per edge per warp)
__global__ void k_aggcsr(const __half* __restrict__ hsh, float* __restrict__ acc,
                         const int* __restrict__ rp, const float2* __restrict__ epk,
                         int N) {
    __shared__ float2 st[8][32];
    int wid  = threadIdx.x >> 5;
    int lane = threadIdx.x & 31;
    int n = (blockIdx.x * blockDim.x + threadIdx.x) >> 5;
    if (n >= N) return;
    int c2 = lane << 1;
    float2 a = __half22float2(*(const __half2*)&hsh[(size_t)n * DD + c2]);  // self
    int beg = rp[n], end = rp[n + 1];
    for (int j0 = beg; j0 < end; j0 += 32) {
        int m = end - j0;
        int jl = j0 + ((lane < m) ? lane : (m - 1));
        st[wid][lane] = __ldg(&epk[jl]);
        __syncwarp();
        if (m >= 32) {
#pragma unroll 8
            for (int k = 0; k < 32; k++) {
                float2 p = st[wid][k];
                int s = __float_as_int(p.x);
                float2 hv = __half22float2(*(const __half2*)&hsh[(size_t)s * DD + c2]);
                a.x += p.y * hv.x;
                a.y += p.y * hv.y;
            }
        } else {
            for (int k = 0; k < m; k++) {
                float2 p = st[wid][k];
                int s = __float_as_int(p.x);
                float2 hv = __half22float2(*(const __half2*)&hsh[(size_t)s * DD + c2]);
                a.x += p.y * hv.x;
                a.y += p.y * hv.y;
            }
        }
        __syncwarp();
    }
    *(float2*)&acc[(size_t)n * DD + c2] = a;
}

// layer 3 matvec: h3s[n] = dv[n] * ( relu(b2 + dv[n]*acc2[n,:]) . W3 )
__global__ void k_gemm3(const float* __restrict__ acc2, const float* __restrict__ W3,
                        const float* __restrict__ b2, const float* __restrict__ dv,
                        float* __restrict__ h3s, int N) {
    int n = (blockIdx.x * blockDim.x + threadIdx.x) >> 5;
    int lane = threadIdx.x & 31;
    if (n >= N) return;
    float d = dv[n];
    const float* xr = acc2 + (size_t)n * DD;
    float v0 = fmaxf(__ldg(&b2[lane])      + d * xr[lane],      0.f);
    float v1 = fmaxf(__ldg(&b2[lane + 32]) + d * xr[lane + 32], 0.f);
    float s = v0 * __ldg(&W3[lane]) + v1 * __ldg(&W3[lane + 32]);
#pragma unroll
    for (int o = 16; o > 0; o >>= 1) s += __shfl_xor_sync(0xffffffffu, s, o);
    if (lane == 0) h3s[n] = d * s;
}

// out[n] = b3 + dv[n] * ( h3s[n] + sum w*h3s[src] )   (warp per node)
__global__ void k_agg3(const float* __restrict__ h3s, float* __restrict__ out,
                       const int* __restrict__ rp, const float2* __restrict__ epk,
                       const float* __restrict__ b3, const float* __restrict__ dv,
                       int N) {
    int n = (blockIdx.x * blockDim.x + threadIdx.x) >> 5;
    int lane = threadIdx.x & 31;
    if (n >= N) return;
    int beg = rp[n], end = rp[n + 1];
    float t = 0.f;
    for (int j = beg + lane; j < end; j += 32) {
        float2 p = __ldg(&epk[j]);
        t += p.y * __ldg(&h3s[__float_as_int(p.x)]);
    }
#pragma unroll
    for (int o = 16; o > 0; o >>= 1) t += __shfl_xor_sync(0xffffffffu, t, o);
    if (lane == 0) out[n] = __ldg(&b3[0]) + dv[n] * (h3s[n] + t);
}

// ---------------- launch ----------------

extern "C" void kernel_launch(void* const* d_in, const int* in_sizes, int n_in,
                              void* d_out, int out_size) {
    const float* feat = (const float*)d_in[0];
    const int*   ei   = (const int*)d_in[1];   // int32 (JAX x64 disabled)
    const float* ev   = (const float*)d_in[2];
    const float* W1   = (const float*)d_in[3];
    const float* b1   = (const float*)d_in[4];
    const float* W2   = (const float*)d_in[5];
    const float* b2   = (const float*)d_in[6];
    const float* W3   = (const float*)d_in[7];
    const float* b3   = (const float*)d_in[8];
    float* out = (float*)d_out;

    int N = in_sizes[0] / DD;
    int E = in_sizes[2];
    const int* src = ei;
    const int* dst = ei + E;

    float *dr, *dv, *ri, *pacc, *ph3s;
    __half* phsh;
    float2* epk;
    int *cnt, *rp, *cur, *bsum;
    cudaGetSymbolAddress((void**)&dr,   g_dr);
    cudaGetSymbolAddress((void**)&cnt,  g_cnt);
    cudaGetSymbolAddress((void**)&rp,   g_rp);
    cudaGetSymbolAddress((void**)&cur,  g_cur);
    cudaGetSymbolAddress((void**)&bsum, g_bsum);
    cudaGetSymbolAddress((void**)&dv,   g_dv);
    cudaGetSymbolAddress((void**)&ri,   g_ri);
    cudaGetSymbolAddress((void**)&epk,  g_epk);
    cudaGetSymbolAddress((void**)&phsh, g_hsh);
    cudaGetSymbolAddress((void**)&pacc, g_acc);
    cudaGetSymbolAddress((void**)&ph3s, g_h3s);

    int nb  = (N + 255) / 256;
    int ebl = (E + 255) / 256;
    int wnb = (N * 32 + 255) / 256;            // warp-per-node grids
    int gemm_blocks = (N + 63) / 64;

    // CSR build + normalization precompute
    k_zero   <<<nb, 256>>>(dr, cnt, N);
    k_pre1   <<<ebl, 256>>>(src, dst, ev, dr, cnt, E);
    k_scan1  <<<SCAN_NB, SCAN_BS>>>(cnt, rp, bsum, N);
    k_scan3  <<<nb, 256>>>(rp, cur, bsum, N, E);
    k_scatter<<<ebl, 256>>>(src, dst, ev, dr, cur, epk, E);
    k_prep   <<<wnb, 256>>>(rp, epk, feat, dv, ri, N);

    // layer 1 (feat normalization folded into epilogue scale via rowinv)
    k_gemm<0><<<gemm_blocks, 256>>>(feat, W1, ri, dv, phsh, N);
    k_aggcsr <<<wnb, 256>>>(phsh, pacc, rp, epk, N);
    // layer 2 (b1 + dinv scaling + relu folded into staging)
    k_gemm<1><<<gemm_blocks, 256>>>(pacc, W2, b1, dv, phsh, N);
    k_aggcsr <<<wnb, 256>>>(phsh, pacc, rp, epk, N);
    // layer 3
    k_gemm3<<<wnb, 256>>>(pacc, W3, b2, dv, ph3s, N);
    k_agg3 <<<wnb, 256>>>(ph3s, out, rp, epk, b3, dv, N);
}

// round 7
// speedup vs baseline: 2.0867x; 1.0277x over previous
#include <cuda_runtime.h>
#include <cuda_fp16.h>

#define NN 100000
#define EE 1600000
#define DD 64
#define SCAN_BS 1024
#define SCAN_NB ((NN + SCAN_BS - 1) / SCAN_BS)   // 98

// ---- scratch (static device globals; no allocation anywhere) ----
__device__ float  g_dr[NN];                    // deg_row
__device__ int    g_cnt[NN];                   // dst histogram
__device__ int    g_rp[NN + 1];                // CSR row_ptr (by dst)
__device__ int    g_cur[NN];                   // scatter cursors
__device__ int    g_bsum[SCAN_NB];             // scan block sums
__device__ float  g_dv[NN];                    // dinv
__device__ float2 g_epk[EE];                   // CSR: packed (src bits, w_hat)
__device__ __align__(16) __half g_hsh[NN * DD];   // fp16: dinv * (x@W1)
__device__ __align__(16) __half g_hsh2[NN * DD];  // fp16: dinv * (x2@W2)
__device__ float g_h3s[NN];

__device__ __forceinline__ float guard1(float v) { return v > 0.f ? v : 1.f; }

__device__ __forceinline__ unsigned f2tf32(float v) {
    unsigned t;
    asm("cvt.rna.tf32.f32 %0, %1;" : "=r"(t) : "f"(v));
    return t;
}

__device__ __forceinline__ void mma_tf32(float* d,
                                         unsigned a0, unsigned a1, unsigned a2, unsigned a3,
                                         unsigned b0, unsigned b1) {
    asm volatile(
        "mma.sync.aligned.m16n8k8.row.col.f32.tf32.tf32.f32 "
        "{%0,%1,%2,%3}, {%4,%5,%6,%7}, {%8,%9}, {%0,%1,%2,%3};"
        : "+f"(d[0]), "+f"(d[1]), "+f"(d[2]), "+f"(d[3])
        : "r"(a0), "r"(a1), "r"(a2), "r"(a3), "r"(b0), "r"(b1));
}

// ---------------- precompute ----------------

__global__ void k_zero(float* __restrict__ dr, int* __restrict__ cnt, int N) {
    int i = blockIdx.x * blockDim.x + threadIdx.x;
    if (i < N) { dr[i] = 0.f; cnt[i] = 0; }
}

__global__ void k_pre1(const int* __restrict__ src, const int* __restrict__ dst,
                       const float* __restrict__ ev,
                       float* __restrict__ dr, int* __restrict__ cnt, int E) {
    int e = blockIdx.x * blockDim.x + threadIdx.x;
    if (e >= E) return;
    atomicAdd(&dr[src[e]], ev[e]);
    atomicAdd(&cnt[dst[e]], 1);
}

// block-level exclusive scan of cnt -> rp ; block totals -> bsum (shfl-based)
__global__ void k_scan1(const int* __restrict__ cnt, int* __restrict__ rp,
                        int* __restrict__ bsum, int N) {
    __shared__ int ws[32];
    int t = threadIdx.x;
    int lane = t & 31, wid = t >> 5;
    int i = blockIdx.x * SCAN_BS + t;
    int v = (i < N) ? cnt[i] : 0;
    int x = v;
#pragma unroll
    for (int o = 1; o < 32; o <<= 1) {
        int y = __shfl_up_sync(0xffffffffu, x, o);
        if (lane >= o) x += y;
    }
    if (lane == 31) ws[wid] = x;
    __syncthreads();
    if (wid == 0) {
        int s = ws[lane];
#pragma unroll
        for (int o = 1; o < 32; o <<= 1) {
            int y = __shfl_up_sync(0xffffffffu, s, o);
            if (lane >= o) s += y;
        }
        ws[lane] = s;
    }
    __syncthreads();
    int incl = x + (wid ? ws[wid - 1] : 0);
    if (i < N) rp[i] = incl - v;
    if (t == SCAN_BS - 1) bsum[blockIdx.x] = incl;
}

// rp[i] += prefix(bsum) ; cursor = rp ; rp[N] = E (redundant per-block scan)
__global__ void k_scan3(int* __restrict__ rp, int* __restrict__ cur,
                        const int* __restrict__ bsum, int N, int E) {
    __shared__ int sh[128];
    int t = threadIdx.x;
    if (t < 128) sh[t] = (t < SCAN_NB) ? bsum[t] : 0;
    __syncthreads();
#pragma unroll
    for (int o = 1; o < 128; o <<= 1) {
        int add = (t >= o && t < 128) ? sh[t - o] : 0;
        __syncthreads();
        if (t < 128) sh[t] += add;
        __syncthreads();
    }
    int i = blockIdx.x * blockDim.x + t;
    if (i >= N) return;
    int blk = i >> 10;
    int off = blk ? sh[blk - 1] : 0;
    int r = rp[i] + off;
    rp[i] = r;
    cur[i] = r;
    if (i == 0) rp[N] = E;
}

__global__ void k_scatter(const int* __restrict__ src, const int* __restrict__ dst,
                          const float* __restrict__ ev, const float* __restrict__ dr,
                          int* __restrict__ cur, float2* __restrict__ epk, int E) {
    int e = blockIdx.x * blockDim.x + threadIdx.x;
    if (e >= E) return;
    int s = src[e], d = dst[e];
    float w = ev[e] / (guard1(__ldg(&dr[s])) * guard1(__ldg(&dr[d])));
    int p = atomicAdd(&cur[d], 1);
    epk[p] = make_float2(__int_as_float(s), w);
}

// warp per node: dinv[n] = rsqrt(1 + sum ew)
__global__ void k_dinv(const int* __restrict__ rp, const float2* __restrict__ epk,
                       float* __restrict__ dv, int N) {
    int n = (blockIdx.x * blockDim.x + threadIdx.x) >> 5;
    int lane = threadIdx.x & 31;
    if (n >= N) return;
    int beg = rp[n], end = rp[n + 1];
    float s = 0.f;
    for (int j = beg + lane; j < end; j += 32) s += __ldg(&epk[j]).y;
#pragma unroll
    for (int o = 16; o > 0; o >>= 1) s += __shfl_xor_sync(0xffffffffu, s, o);
    if (lane == 0) dv[n] = rsqrtf(1.f + s);
}

// ---------------- layers ----------------

#define XA 68   // xs stride: conflict-free A-frag loads
#define WB 72   // Ws stride: conflict-free B-frag loads

// Layer 1 GEMM: hsh[row,c] = half( (dv[row]/rowsum(feat[row])) * (feat@W1)[c] )
// rowsum computed in-kernel from the staged tile.
__global__ void k_gemm0(const float* __restrict__ in, const float* __restrict__ W,
                        const float* __restrict__ dv, __half* __restrict__ hsh, int N) {
    __shared__ float Ws[DD * WB];
    __shared__ float xs[DD * XA];
    __shared__ float dvs[64];
    __shared__ float scal[64];
    int tid = threadIdx.x;
    int row0 = blockIdx.x * 64;

#pragma unroll
    for (int it = 0; it < 16; it++) {
        int i = it * 256 + tid;
        Ws[(i >> 6) * WB + (i & 63)] = __uint_as_float(f2tf32(W[i]));
    }
    if (tid < 64) {
        int row = row0 + tid;
        dvs[tid] = (row < N) ? dv[row] : 0.f;
    }
    // stage raw feat
#pragma unroll
    for (int it = 0; it < 16; it++) {
        int i = it * 256 + tid;
        int r = i >> 6, c = i & 63;
        int row = row0 + r;
        xs[r * XA + c] = (row < N) ? in[(size_t)row * DD + c] : 0.f;
    }
    __syncthreads();
    // per-row sums -> scal = dv/rowsum
    if (tid < 64) {
        float s = 0.f;
        const float* xr = &xs[tid * XA];
#pragma unroll
        for (int c = 0; c < DD; c++) s += xr[c];
        scal[tid] = dvs[tid] / fmaxf(s, 1e-30f);
    }
    __syncthreads();
    // cvt staged tile to tf32 in place
#pragma unroll
    for (int it = 0; it < 16; it++) {
        int i = it * 256 + tid;
        int r = i >> 6, c = i & 63;
        xs[r * XA + c] = __uint_as_float(f2tf32(xs[r * XA + c]));
    }
    __syncthreads();

    int warp = tid >> 5, lane = tid & 31;
    int m0 = (warp & 3) << 4;
    int n0 = (warp >> 2) << 5;
    int g = lane >> 2, tig = lane & 3;
    float acc[4][4];
#pragma unroll
    for (int s = 0; s < 4; s++) { acc[s][0] = acc[s][1] = acc[s][2] = acc[s][3] = 0.f; }
#pragma unroll
    for (int ks = 0; ks < 8; ks++) {
        int k0 = ks << 3;
        unsigned a0 = __float_as_uint(xs[(m0 + g)     * XA + k0 + tig]);
        unsigned a1 = __float_as_uint(xs[(m0 + g + 8) * XA + k0 + tig]);
        unsigned a2 = __float_as_uint(xs[(m0 + g)     * XA + k0 + tig + 4]);
        unsigned a3 = __float_as_uint(xs[(m0 + g + 8) * XA + k0 + tig + 4]);
#pragma unroll
        for (int sub = 0; sub < 4; sub++) {
            int n = n0 + (sub << 3) + g;
            unsigned b0 = __float_as_uint(Ws[(k0 + tig)     * WB + n]);
            unsigned b1 = __float_as_uint(Ws[(k0 + tig + 4) * WB + n]);
            mma_tf32(acc[sub], a0, a1, a2, a3, b0, b1);
        }
    }
    int rlo = m0 + g, rhi = m0 + g + 8;
    int row_lo = row0 + rlo, row_hi = row0 + rhi;
    float s0 = scal[rlo], s1 = scal[rhi];
#pragma unroll
    for (int sub = 0; sub < 4; sub++) {
        int col = n0 + (sub << 3) + (tig << 1);
        if (row_lo < N) {
            __half2 h = __floats2half2_rn(s0 * acc[sub][0], s0 * acc[sub][1]);
            *(__half2*)&hsh[(size_t)row_lo * DD + col] = h;
        }
        if (row_hi < N) {
            __half2 h = __floats2half2_rn(s1 * acc[sub][2], s1 * acc[sub][3]);
            *(__half2*)&hsh[(size_t)row_hi * DD + col] = h;
        }
    }
}

// Fused layer 2: per 64-row block, aggregate from hsh (CSR gather), apply
// relu(b1 + dv*a), stage tf32, then mma with W2; out = half(dv * (x2@W2)).
__global__ void k_agg_gemm(const __half* __restrict__ hsh,
                           const int* __restrict__ rp, const float2* __restrict__ epk,
                           const float* __restrict__ W, const float* __restrict__ b,
                           const float* __restrict__ dv,
                           __half* __restrict__ out, int N) {
    __shared__ float Ws[DD * WB];
    __shared__ float xs[DD * XA];
    __shared__ float dvs[64];
    __shared__ float2 st[8][32];
    int tid = threadIdx.x;
    int warp = tid >> 5, lane = tid & 31;
    int row0 = blockIdx.x * 64;

#pragma unroll
    for (int it = 0; it < 16; it++) {
        int i = it * 256 + tid;
        Ws[(i >> 6) * WB + (i & 63)] = __uint_as_float(f2tf32(W[i]));
    }
    if (tid < 64) {
        int row = row0 + tid;
        dvs[tid] = (row < N) ? dv[row] : 0.f;
    }
    __syncthreads();

    // aggregation phase: warp handles rows warp*8 .. warp*8+7
    int c2 = lane << 1;
    float bx = __ldg(&b[c2]), by = __ldg(&b[c2 + 1]);
#pragma unroll
    for (int q = 0; q < 8; q++) {
        int r = (warp << 3) + q;
        int n = row0 + r;
        float vx = 0.f, vy = 0.f;
        if (n < N) {
            float2 a = __half22float2(*(const __half2*)&hsh[(size_t)n * DD + c2]);
            int beg = rp[n], end = rp[n + 1];
            for (int j0 = beg; j0 < end; j0 += 32) {
                int m = end - j0;
                int jl = j0 + ((lane < m) ? lane : (m - 1));
                st[warp][lane] = __ldg(&epk[jl]);
                __syncwarp();
                if (m >= 32) {
#pragma unroll 8
                    for (int k = 0; k < 32; k++) {
                        float2 p = st[warp][k];
                        int s = __float_as_int(p.x);
                        float2 hv = __half22float2(*(const __half2*)&hsh[(size_t)s * DD + c2]);
                        a.x += p.y * hv.x;
                        a.y += p.y * hv.y;
                    }
                } else {
                    for (int k = 0; k < m; k++) {
                        float2 p = st[warp][k];
                        int s = __float_as_int(p.x);
                        float2 hv = __half22float2(*(const __half2*)&hsh[(size_t)s * DD + c2]);
                        a.x += p.y * hv.x;
                        a.y += p.y * hv.y;
                    }
                }
                __syncwarp();
            }
            float dn = dvs[r];
            vx = fmaxf(bx + dn * a.x, 0.f);
            vy = fmaxf(by + dn * a.y, 0.f);
        }
        xs[r * XA + c2]     = __uint_as_float(f2tf32(vx));
        xs[r * XA + c2 + 1] = __uint_as_float(f2tf32(vy));
    }
    __syncthreads();

    int m0 = (warp & 3) << 4;
    int n0 = (warp >> 2) << 5;
    int g = lane >> 2, tig = lane & 3;
    float acc[4][4];
#pragma unroll
    for (int s = 0; s < 4; s++) { acc[s][0] = acc[s][1] = acc[s][2] = acc[s][3] = 0.f; }
#pragma unroll
    for (int ks = 0; ks < 8; ks++) {
        int k0 = ks << 3;
        unsigned a0 = __float_as_uint(xs[(m0 + g)     * XA + k0 + tig]);
        unsigned a1 = __float_as_uint(xs[(m0 + g + 8) * XA + k0 + tig]);
        unsigned a2 = __float_as_uint(xs[(m0 + g)     * XA + k0 + tig + 4]);
        unsigned a3 = __float_as_uint(xs[(m0 + g + 8) * XA + k0 + tig + 4]);
#pragma unroll
        for (int sub = 0; sub < 4; sub++) {
            int n = n0 + (sub << 3) + g;
            unsigned b0 = __float_as_uint(Ws[(k0 + tig)     * WB + n]);
            unsigned b1 = __float_as_uint(Ws[(k0 + tig + 4) * WB + n]);
            mma_tf32(acc[sub], a0, a1, a2, a3, b0, b1);
        }
    }
    int rlo = m0 + g, rhi = m0 + g + 8;
    int row_lo = row0 + rlo, row_hi = row0 + rhi;
    float s0 = dvs[rlo], s1 = dvs[rhi];
#pragma unroll
    for (int sub = 0; sub < 4; sub++) {
        int col = n0 + (sub << 3) + (tig << 1);
        if (row_lo < N) {
            __half2 h = __floats2half2_rn(s0 * acc[sub][0], s0 * acc[sub][1]);
            *(__half2*)&out[(size_t)row_lo * DD + col] = h;
        }
        if (row_hi < N) {
            __half2 h = __floats2half2_rn(s1 * acc[sub][2], s1 * acc[sub][3]);
            *(__half2*)&out[(size_t)row_hi * DD + col] = h;
        }
    }
}

// Fused layer 3 head: warp per node — aggregate from hsh2, then
// h3s[n] = dv[n] * ( relu(b2 + dv[n]*a) . W3 )
__global__ void k_agg_dot(const __half* __restrict__ hsh2,
                          const int* __restrict__ rp, const float2* __restrict__ epk,
                          const float* __restrict__ W3, const float* __restrict__ b2,
                          const float* __restrict__ dv,
                          float* __restrict__ h3s, int N) {
    __shared__ float2 st[8][32];
    int wid  = threadIdx.x >> 5;
    int lane = threadIdx.x & 31;
    int n = (blockIdx.x * blockDim.x + threadIdx.x) >> 5;
    if (n >= N) return;
    int c2 = lane << 1;
    float2 a = __half22float2(*(const __half2*)&hsh2[(size_t)n * DD + c2]);
    int beg = rp[n], end = rp[n + 1];
    for (int j0 = beg; j0 < end; j0 += 32) {
        int m = end - j0;
        int jl = j0 + ((lane < m) ? lane : (m - 1));
        st[wid][lane] = __ldg(&epk[jl]);
        __syncwarp();
        if (m >= 32) {
#pragma unroll 8
            for (int k = 0; k < 32; k++) {
                float2 p = st[wid][k];
                int s = __float_as_int(p.x);
                float2 hv = __half22float2(*(const __half2*)&hsh2[(size_t)s * DD + c2]);
                a.x += p.y * hv.x;
                a.y += p.y * hv.y;
            }
        } else {
            for (int k = 0; k < m; k++) {
                float2 p = st[wid][k];
                int s = __float_as_int(p.x);
                float2 hv = __half22float2(*(const __half2*)&hsh2[(size_t)s * DD + c2]);
                a.x += p.y * hv.x;
                a.y += p.y * hv.y;
            }
        }
        __syncwarp();
    }
    float d = dv[n];
    float v0 = fmaxf(__ldg(&b2[c2])     + d * a.x, 0.f);
    float v1 = fmaxf(__ldg(&b2[c2 + 1]) + d * a.y, 0.f);
    float s = v0 * __ldg(&W3[c2]) + v1 * __ldg(&W3[c2 + 1]);
#pragma unroll
    for (int o = 16; o > 0; o >>= 1) s += __shfl_xor_sync(0xffffffffu, s, o);
    if (lane == 0) h3s[n] = d * s;
}

// out[n] = b3 + dv[n] * ( h3s[n] + sum w*h3s[src] )   (warp per node)
__global__ void k_agg3(const float* __restrict__ h3s, float* __restrict__ out,
                       const int* __restrict__ rp, const float2* __restrict__ epk,
                       const float* __restrict__ b3, const float* __restrict__ dv,
                       int N) {
    int n = (blockIdx.x * blockDim.x + threadIdx.x) >> 5;
    int lane = threadIdx.x & 31;
    if (n >= N) return;
    int beg = rp[n], end = rp[n + 1];
    float t = 0.f;
    for (int j = beg + lane; j < end; j += 32) {
        float2 p = __ldg(&epk[j]);
        t += p.y * __ldg(&h3s[__float_as_int(p.x)]);
    }
#pragma unroll
    for (int o = 16; o > 0; o >>= 1) t += __shfl_xor_sync(0xffffffffu, t, o);
    if (lane == 0) out[n] = __ldg(&b3[0]) + dv[n] * (h3s[n] + t);
}

// ---------------- launch ----------------

extern "C" void kernel_launch(void* const* d_in, const int* in_sizes, int n_in,
                              void* d_out, int out_size) {
    const float* feat = (const float*)d_in[0];
    const int*   ei   = (const int*)d_in[1];   // int32 (JAX x64 disabled)
    const float* ev   = (const float*)d_in[2];
    const float* W1   = (const float*)d_in[3];
    const float* b1   = (const float*)d_in[4];
    const float* W2   = (const float*)d_in[5];
    const float* b2   = (const float*)d_in[6];
    const float* W3   = (const float*)d_in[7];
    const float* b3   = (const float*)d_in[8];
    float* out = (float*)d_out;

    int N = in_sizes[0] / DD;
    int E = in_sizes[2];
    const int* src = ei;
    const int* dst = ei + E;

    float *dr, *dv, *ph3s;
    __half *phsh, *phsh2;
    float2* epk;
    int *cnt, *rp, *cur, *bsum;
    cudaGetSymbolAddress((void**)&dr,    g_dr);
    cudaGetSymbolAddress((void**)&cnt,   g_cnt);
    cudaGetSymbolAddress((void**)&rp,    g_rp);
    cudaGetSymbolAddress((void**)&cur,   g_cur);
    cudaGetSymbolAddress((void**)&bsum,  g_bsum);
    cudaGetSymbolAddress((void**)&dv,    g_dv);
    cudaGetSymbolAddress((void**)&epk,   g_epk);
    cudaGetSymbolAddress((void**)&phsh,  g_hsh);
    cudaGetSymbolAddress((void**)&phsh2, g_hsh2);
    cudaGetSymbolAddress((void**)&ph3s,  g_h3s);

    int nb  = (N + 255) / 256;
    int ebl = (E + 255) / 256;
    int wnb = (N * 32 + 255) / 256;            // warp-per-node grids
    int gemm_blocks = (N + 63) / 64;

    // CSR build + normalization precompute
    k_zero   <<<nb, 256>>>(dr, cnt, N);
    k_pre1   <<<ebl, 256>>>(src, dst, ev, dr, cnt, E);
    k_scan1  <<<SCAN_NB, SCAN_BS>>>(cnt, rp, bsum, N);
    k_scan3  <<<nb, 256>>>(rp, cur, bsum, N, E);
    k_scatter<<<ebl, 256>>>(src, dst, ev, dr, cur, epk, E);
    k_dinv   <<<wnb, 256>>>(rp, epk, dv, N);

    // layer 1: feat -> hsh (rowsum folded in-kernel)
    k_gemm0   <<<gemm_blocks, 256>>>(feat, W1, dv, phsh, N);
    // layer 2: fused agg(hsh) + relu(b1+dv*a) + GEMM(W2) -> hsh2
    k_agg_gemm<<<gemm_blocks, 256>>>(phsh, rp, epk, W2, b1, dv, phsh2, N);
    // layer 3 head: fused agg(hsh2) + relu(b2+dv*a).W3 -> h3s
    k_agg_dot <<<wnb, 256>>>(phsh2, rp, epk, W3, b2, dv, ph3s, N);
    // final aggregation
    k_agg3    <<<wnb, 256>>>(ph3s, out, rp, epk, b3, dv, N);
}

// round 8
// speedup vs baseline: 2.1112x; 1.0118x over previous
#include <cuda_runtime.h>
#include <cuda_fp16.h>

#define NN 100000
#define EE 1600000
#define DD 64
#define SCAN_BS 1024
#define SCAN_NB ((NN + SCAN_BS - 1) / SCAN_BS)   // 98

// ---- scratch (static device globals; no allocation anywhere) ----
// zeroed as one block each launch: [dr | dg | cnt]
__device__ float    g_zbuf[3 * NN];
__device__ int      g_rp[NN + 1];              // CSR row_ptr (by dst)
__device__ int      g_cur[NN];                 // scatter cursors
__device__ int      g_bsum[SCAN_NB];           // scan block sums
__device__ unsigned g_epk[EE];                 // CSR: (src<<15) | fp16(w) sans sign
__device__ __align__(16) __half g_hsh[NN * DD];   // fp16: dinv * (x@W1)
__device__ __align__(16) __half g_hsh2[NN * DD];  // fp16: dinv * (x2@W2)
__device__ float g_h3s[NN];

__device__ __forceinline__ float guard1(float v) { return v > 0.f ? v : 1.f; }

__device__ __forceinline__ unsigned f2tf32(float v) {
    unsigned t;
    asm("cvt.rna.tf32.f32 %0, %1;" : "=r"(t) : "f"(v));
    return t;
}

__device__ __forceinline__ void mma_tf32(float* d,
                                         unsigned a0, unsigned a1, unsigned a2, unsigned a3,
                                         unsigned b0, unsigned b1) {
    asm volatile(
        "mma.sync.aligned.m16n8k8.row.col.f32.tf32.tf32.f32 "
        "{%0,%1,%2,%3}, {%4,%5,%6,%7}, {%8,%9}, {%0,%1,%2,%3};"
        : "+f"(d[0]), "+f"(d[1]), "+f"(d[2]), "+f"(d[3])
        : "r"(a0), "r"(a1), "r"(a2), "r"(a3), "r"(b0), "r"(b1));
}

__device__ __forceinline__ void dec_epk(unsigned v, int& s, float& w) {
    s = (int)(v >> 15);
    w = __half2float(__ushort_as_half((unsigned short)(v & 0x7FFFu)));
}

// ---------------- precompute ----------------

__global__ void k_pre1(const int* __restrict__ src, const int* __restrict__ dst,
                       const float* __restrict__ ev,
                       float* __restrict__ dr, int* __restrict__ cnt, int E) {
    int e = blockIdx.x * blockDim.x + threadIdx.x;
    if (e >= E) return;
    atomicAdd(&dr[src[e]], ev[e]);
    atomicAdd(&cnt[dst[e]], 1);
}

// block-level exclusive scan of cnt -> rp ; block totals -> bsum (shfl-based)
__global__ void k_scan1(const int* __restrict__ cnt, int* __restrict__ rp,
                        int* __restrict__ bsum, int N) {
    __shared__ int ws[32];
    int t = threadIdx.x;
    int lane = t & 31, wid = t >> 5;
    int i = blockIdx.x * SCAN_BS + t;
    int v = (i < N) ? cnt[i] : 0;
    int x = v;
#pragma unroll
    for (int o = 1; o < 32; o <<= 1) {
        int y = __shfl_up_sync(0xffffffffu, x, o);
        if (lane >= o) x += y;
    }
    if (lane == 31) ws[wid] = x;
    __syncthreads();
    if (wid == 0) {
        int s = ws[lane];
#pragma unroll
        for (int o = 1; o < 32; o <<= 1) {
            int y = __shfl_up_sync(0xffffffffu, s, o);
            if (lane >= o) s += y;
        }
        ws[lane] = s;
    }
    __syncthreads();
    int incl = x + (wid ? ws[wid - 1] : 0);
    if (i < N) rp[i] = incl - v;
    if (t == SCAN_BS - 1) bsum[blockIdx.x] = incl;
}

// rp[i] += prefix(bsum) ; cursor = rp ; rp[N] = E (redundant per-block scan)
__global__ void k_scan3(int* __restrict__ rp, int* __restrict__ cur,
                        const int* __restrict__ bsum, int N, int E) {
    __shared__ int sh[128];
    int t = threadIdx.x;
    if (t < 128) sh[t] = (t < SCAN_NB) ? bsum[t] : 0;
    __syncthreads();
#pragma unroll
    for (int o = 1; o < 128; o <<= 1) {
        int add = (t >= o && t < 128) ? sh[t - o] : 0;
        __syncthreads();
        if (t < 128) sh[t] += add;
        __syncthreads();
    }
    int i = blockIdx.x * blockDim.x + t;
    if (i >= N) return;
    int blk = i >> 10;
    int off = blk ? sh[blk - 1] : 0;
    int r = rp[i] + off;
    rp[i] = r;
    cur[i] = r;
    if (i == 0) rp[N] = E;
}

// fused: w_hat compute + deg accumulation + packed CSR scatter
__global__ void k_scatter(const int* __restrict__ src, const int* __restrict__ dst,
                          const float* __restrict__ ev, const float* __restrict__ dr,
                          float* __restrict__ dg, int* __restrict__ cur,
                          unsigned* __restrict__ epk, int E) {
    int e = blockIdx.x * blockDim.x + threadIdx.x;
    if (e >= E) return;
    int s = src[e], d = dst[e];
    float w = ev[e] / (guard1(__ldg(&dr[s])) * guard1(__ldg(&dr[d])));
    atomicAdd(&dg[d], w);
    int p = atomicAdd(&cur[d], 1);
    unsigned hb = (unsigned)__half_as_ushort(__float2half_rn(w));  // w>0: bit15=0
    epk[p] = ((unsigned)s << 15) | hb;
}

// ---------------- layers ----------------

#define XA 68   // xs stride: conflict-free A-frag loads
#define WB 72   // Ws stride: conflict-free B-frag loads

// Layer 1 GEMM: hsh[row,c] = half( (dv[row]/rowsum(feat[row])) * (feat@W1)[c] )
__global__ void k_gemm0(const float* __restrict__ in, const float* __restrict__ W,
                        const float* __restrict__ dg, __half* __restrict__ hsh, int N) {
    __shared__ float Ws[DD * WB];
    __shared__ float xs[DD * XA];
    __shared__ float scal[64];
    int tid = threadIdx.x;
    int row0 = blockIdx.x * 64;

#pragma unroll
    for (int it = 0; it < 16; it++) {
        int i = it * 256 + tid;
        Ws[(i >> 6) * WB + (i & 63)] = __uint_as_float(f2tf32(W[i]));
    }
    // stage raw feat
#pragma unroll
    for (int it = 0; it < 16; it++) {
        int i = it * 256 + tid;
        int r = i >> 6, c = i & 63;
        int row = row0 + r;
        xs[r * XA + c] = (row < N) ? in[(size_t)row * DD + c] : 0.f;
    }
    __syncthreads();
    // per-row sums -> scal = dv/rowsum  (dv computed inline from dg)
    if (tid < 64) {
        int row = row0 + tid;
        float s = 0.f;
        const float* xr = &xs[tid * XA];
#pragma unroll
        for (int c = 0; c < DD; c++) s += xr[c];
        float dv = (row < N) ? rsqrtf(1.f + dg[row]) : 0.f;
        scal[tid] = dv / fmaxf(s, 1e-30f);
    }
    __syncthreads();
    // cvt staged tile to tf32 in place
#pragma unroll
    for (int it = 0; it < 16; it++) {
        int i = it * 256 + tid;
        int r = i >> 6, c = i & 63;
        xs[r * XA + c] = __uint_as_float(f2tf32(xs[r * XA + c]));
    }
    __syncthreads();

    int warp = tid >> 5, lane = tid & 31;
    int m0 = (warp & 3) << 4;
    int n0 = (warp >> 2) << 5;
    int g = lane >> 2, tig = lane & 3;
    float acc[4][4];
#pragma unroll
    for (int s = 0; s < 4; s++) { acc[s][0] = acc[s][1] = acc[s][2] = acc[s][3] = 0.f; }
#pragma unroll
    for (int ks = 0; ks < 8; ks++) {
        int k0 = ks << 3;
        unsigned a0 = __float_as_uint(xs[(m0 + g)     * XA + k0 + tig]);
        unsigned a1 = __float_as_uint(xs[(m0 + g + 8) * XA + k0 + tig]);
        unsigned a2 = __float_as_uint(xs[(m0 + g)     * XA + k0 + tig + 4]);
        unsigned a3 = __float_as_uint(xs[(m0 + g + 8) * XA + k0 + tig + 4]);
#pragma unroll
        for (int sub = 0; sub < 4; sub++) {
            int n = n0 + (sub << 3) + g;
            unsigned b0 = __float_as_uint(Ws[(k0 + tig)     * WB + n]);
            unsigned b1 = __float_as_uint(Ws[(k0 + tig + 4) * WB + n]);
            mma_tf32(acc[sub], a0, a1, a2, a3, b0, b1);
        }
    }
    int rlo = m0 + g, rhi = m0 + g + 8;
    int row_lo = row0 + rlo, row_hi = row0 + rhi;
    float s0 = scal[rlo], s1 = scal[rhi];
#pragma unroll
    for (int sub = 0; sub < 4; sub++) {
        int col = n0 + (sub << 3) + (tig << 1);
        if (row_lo < N) {
            __half2 h = __floats2half2_rn(s0 * acc[sub][0], s0 * acc[sub][1]);
            *(__half2*)&hsh[(size_t)row_lo * DD + col] = h;
        }
        if (row_hi < N) {
            __half2 h = __floats2half2_rn(s1 * acc[sub][2], s1 * acc[sub][3]);
            *(__half2*)&hsh[(size_t)row_hi * DD + col] = h;
        }
    }
}

// Fused layer 2: aggregate from hsh (packed CSR gather), relu(b1+dv*a),
// tf32 stage, mma with W2; out = half(dv * (x2@W2)).
__global__ void k_agg_gemm(const __half* __restrict__ hsh,
                           const int* __restrict__ rp, const unsigned* __restrict__ epk,
                           const float* __restrict__ W, const float* __restrict__ b,
                           const float* __restrict__ dg,
                           __half* __restrict__ out, int N) {
    __shared__ float Ws[DD * WB];
    __shared__ float xs[DD * XA];
    __shared__ float dvs[64];
    __shared__ unsigned st[8][32];
    int tid = threadIdx.x;
    int warp = tid >> 5, lane = tid & 31;
    int row0 = blockIdx.x * 64;

#pragma unroll
    for (int it = 0; it < 16; it++) {
        int i = it * 256 + tid;
        Ws[(i >> 6) * WB + (i & 63)] = __uint_as_float(f2tf32(W[i]));
    }
    if (tid < 64) {
        int row = row0 + tid;
        dvs[tid] = (row < N) ? rsqrtf(1.f + dg[row]) : 0.f;
    }
    __syncthreads();

    int c2 = lane << 1;
    float bx = __ldg(&b[c2]), by = __ldg(&b[c2 + 1]);
#pragma unroll
    for (int q = 0; q < 8; q++) {
        int r = (warp << 3) + q;
        int n = row0 + r;
        float vx = 0.f, vy = 0.f;
        if (n < N) {
            float2 a = __half22float2(*(const __half2*)&hsh[(size_t)n * DD + c2]);
            int beg = rp[n], end = rp[n + 1];
            for (int j0 = beg; j0 < end; j0 += 32) {
                int m = end - j0;
                int jl = j0 + ((lane < m) ? lane : (m - 1));
                st[warp][lane] = __ldg(&epk[jl]);
                __syncwarp();
                if (m >= 32) {
#pragma unroll 8
                    for (int k = 0; k < 32; k++) {
                        int s; float w; dec_epk(st[warp][k], s, w);
                        float2 hv = __half22float2(*(const __half2*)&hsh[(size_t)s * DD + c2]);
                        a.x += w * hv.x;
                        a.y += w * hv.y;
                    }
                } else {
                    for (int k = 0; k < m; k++) {
                        int s; float w; dec_epk(st[warp][k], s, w);
                        float2 hv = __half22float2(*(const __half2*)&hsh[(size_t)s * DD + c2]);
                        a.x += w * hv.x;
                        a.y += w * hv.y;
                    }
                }
                __syncwarp();
            }
            float dn = dvs[r];
            vx = fmaxf(bx + dn * a.x, 0.f);
            vy = fmaxf(by + dn * a.y, 0.f);
        }
        xs[r * XA + c2]     = __uint_as_float(f2tf32(vx));
        xs[r * XA + c2 + 1] = __uint_as_float(f2tf32(vy));
    }
    __syncthreads();

    int m0 = (warp & 3) << 4;
    int n0 = (warp >> 2) << 5;
    int g = lane >> 2, tig = lane & 3;
    float acc[4][4];
#pragma unroll
    for (int s = 0; s < 4; s++) { acc[s][0] = acc[s][1] = acc[s][2] = acc[s][3] = 0.f; }
#pragma unroll
    for (int ks = 0; ks < 8; ks++) {
        int k0 = ks << 3;
        unsigned a0 = __float_as_uint(xs[(m0 + g)     * XA + k0 + tig]);
        unsigned a1 = __float_as_uint(xs[(m0 + g + 8) * XA + k0 + tig]);
        unsigned a2 = __float_as_uint(xs[(m0 + g)     * XA + k0 + tig + 4]);
        unsigned a3 = __float_as_uint(xs[(m0 + g + 8) * XA + k0 + tig + 4]);
#pragma unroll
        for (int sub = 0; sub < 4; sub++) {
            int n = n0 + (sub << 3) + g;
            unsigned b0 = __float_as_uint(Ws[(k0 + tig)     * WB + n]);
            unsigned b1 = __float_as_uint(Ws[(k0 + tig + 4) * WB + n]);
            mma_tf32(acc[sub], a0, a1, a2, a3, b0, b1);
        }
    }
    int rlo = m0 + g, rhi = m0 + g + 8;
    int row_lo = row0 + rlo, row_hi = row0 + rhi;
    float s0 = dvs[rlo], s1 = dvs[rhi];
#pragma unroll
    for (int sub = 0; sub < 4; sub++) {
        int col = n0 + (sub << 3) + (tig << 1);
        if (row_lo < N) {
            __half2 h = __floats2half2_rn(s0 * acc[sub][0], s0 * acc[sub][1]);
            *(__half2*)&out[(size_t)row_lo * DD + col] = h;
        }
        if (row_hi < N) {
            __half2 h = __floats2half2_rn(s1 * acc[sub][2], s1 * acc[sub][3]);
            *(__half2*)&out[(size_t)row_hi * DD + col] = h;
        }
    }
}

// Fused layer 3 head: warp per node — aggregate from hsh2, then
// h3s[n] = dv[n] * ( relu(b2 + dv[n]*a) . W3 )
__global__ void k_agg_dot(const __half* __restrict__ hsh2,
                          const int* __restrict__ rp, const unsigned* __restrict__ epk,
                          const float* __restrict__ W3, const float* __restrict__ b2,
                          const float* __restrict__ dg,
                          float* __restrict__ h3s, int N) {
    __shared__ unsigned st[8][32];
    int wid  = threadIdx.x >> 5;
    int lane = threadIdx.x & 31;
    int n = (blockIdx.x * blockDim.x + threadIdx.x) >> 5;
    if (n >= N) return;
    int c2 = lane << 1;
    float2 a = __half22float2(*(const __half2*)&hsh2[(size_t)n * DD + c2]);
    int beg = rp[n], end = rp[n + 1];
    for (int j0 = beg; j0 < end; j0 += 32) {
        int m = end - j0;
        int jl = j0 + ((lane < m) ? lane : (m - 1));
        st[wid][lane] = __ldg(&epk[jl]);
        __syncwarp();
        if (m >= 32) {
#pragma unroll 8
            for (int k = 0; k < 32; k++) {
                int s; float w; dec_epk(st[wid][k], s, w);
                float2 hv = __half22float2(*(const __half2*)&hsh2[(size_t)s * DD + c2]);
                a.x += w * hv.x;
                a.y += w * hv.y;
            }
        } else {
            for (int k = 0; k < m; k++) {
                int s; float w; dec_epk(st[wid][k], s, w);
                float2 hv = __half22float2(*(const __half2*)&hsh2[(size_t)s * DD + c2]);
                a.x += w * hv.x;
                a.y += w * hv.y;
            }
        }
        __syncwarp();
    }
    float d = rsqrtf(1.f + __ldg(&dg[n]));
    float v0 = fmaxf(__ldg(&b2[c2])     + d * a.x, 0.f);
    float v1 = fmaxf(__ldg(&b2[c2 + 1]) + d * a.y, 0.f);
    float s = v0 * __ldg(&W3[c2]) + v1 * __ldg(&W3[c2 + 1]);
#pragma unroll
    for (int o = 16; o > 0; o >>= 1) s += __shfl_xor_sync(0xffffffffu, s, o);
    if (lane == 0) h3s[n] = d * s;
}

// out[n] = b3 + dv[n] * ( h3s[n] + sum w*h3s[src] )   (warp per node)
__global__ void k_agg3(const float* __restrict__ h3s, float* __restrict__ out,
                       const int* __restrict__ rp, const unsigned* __restrict__ epk,
                       const float* __restrict__ b3, const float* __restrict__ dg,
                       int N) {
    int n = (blockIdx.x * blockDim.x + threadIdx.x) >> 5;
    int lane = threadIdx.x & 31;
    if (n >= N) return;
    int beg = rp[n], end = rp[n + 1];
    float t = 0.f;
    for (int j = beg + lane; j < end; j += 32) {
        int s; float w; dec_epk(__ldg(&epk[j]), s, w);
        t += w * __ldg(&h3s[s]);
    }
#pragma unroll
    for (int o = 16; o > 0; o >>= 1) t += __shfl_xor_sync(0xffffffffu, t, o);
    if (lane == 0) {
        float d = rsqrtf(1.f + __ldg(&dg[n]));
        out[n] = __ldg(&b3[0]) + d * (h3s[n] + t);
    }
}

// ---------------- launch ----------------

extern "C" void kernel_launch(void* const* d_in, const int* in_sizes, int n_in,
                              void* d_out, int out_size) {
    const float* feat = (const float*)d_in[0];
    const int*   ei   = (const int*)d_in[1];   // int32 (JAX x64 disabled)
    const float* ev   = (const float*)d_in[2];
    const float* W1   = (const float*)d_in[3];
    const float* b1   = (const float*)d_in[4];
    const float* W2   = (const float*)d_in[5];
    const float* b2   = (const float*)d_in[6];
    const float* W3   = (const float*)d_in[7];
    const float* b3   = (const float*)d_in[8];
    float* out = (float*)d_out;

    int N = in_sizes[0] / DD;
    int E = in_sizes[2];
    const int* src = ei;
    const int* dst = ei + E;

    float *zbuf, *ph3s;
    __half *phsh, *phsh2;
    unsigned* epk;
    int *rp, *cur, *bsum;
    cudaGetSymbolAddress((void**)&zbuf,  g_zbuf);
    cudaGetSymbolAddress((void**)&rp,    g_rp);
    cudaGetSymbolAddress((void**)&cur,   g_cur);
    cudaGetSymbolAddress((void**)&bsum,  g_bsum);
    cudaGetSymbolAddress((void**)&epk,   g_epk);
    cudaGetSymbolAddress((void**)&phsh,  g_hsh);
    cudaGetSymbolAddress((void**)&phsh2, g_hsh2);
    cudaGetSymbolAddress((void**)&ph3s,  g_h3s);

    float* dr = zbuf;            // deg_row
    float* dg = zbuf + NN;       // deg (A_hat col sums into dst)
    int*   cnt = (int*)(zbuf + 2 * NN);

    int nb  = (N + 255) / 256;
    int ebl = (E + 255) / 256;
    int wnb = (N * 32 + 255) / 256;
    int gemm_blocks = (N + 63) / 64;

    // zero dr/dg/cnt in one memset node
    cudaMemsetAsync(zbuf, 0, 3 * NN * sizeof(float), 0);

    // CSR build (+deg fused into scatter)
    k_pre1   <<<ebl, 256>>>(src, dst, ev, dr, cnt, E);
    k_scan1  <<<SCAN_NB, SCAN_BS>>>(cnt, rp, bsum, N);
    k_scan3  <<<nb, 256>>>(rp, cur, bsum, N, E);
    k_scatter<<<ebl, 256>>>(src, dst, ev, dr, dg, cur, epk, E);

    // layer 1: feat -> hsh (rowsum + dinv folded in-kernel)
    k_gemm0   <<<gemm_blocks, 256>>>(feat, W1, dg, phsh, N);
    // layer 2: fused agg(hsh) + relu(b1+dv*a) + GEMM(W2) -> hsh2
    k_agg_gemm<<<gemm_blocks, 256>>>(phsh, rp, epk, W2, b1, dg, phsh2, N);
    // layer 3 head: fused agg(hsh2) + relu(b2+dv*a).W3 -> h3s
    k_agg_dot <<<wnb, 256>>>(phsh2, rp, epk, W3, b2, dg, ph3s, N);
    // final aggregation
    k_agg3    <<<wnb, 256>>>(ph3s, out, rp, epk, b3, dg, N);
}